// round 2
// baseline (speedup 1.0000x reference)
#include <cuda_runtime.h>
#include <cstdint>
#include <cstdio>

#define TT 8
#define BB 8
#define CINC 128
#define HID 64
#define GG 256      // 4*HID gate channels
#define HWSZ 1024   // 32*32
#define OUTC 64

// ---------------- scratch (device globals; no allocations allowed) ----------
__device__ float g_gates[(size_t)2 * TT * BB * GG * HWSZ];   // [dir][t][b][256][1024] (134MB)
__device__ float g_xs1[(size_t)TT * BB * 2 * HID * HWSZ];    // layer-1 input  [t][b][128][1024]
__device__ float g_h[(size_t)2 * BB * HID * HWSZ];           // [dir][b][64][1024]
__device__ float g_c[(size_t)2 * BB * HID * HWSZ];
__device__ float g_last[(size_t)BB * 2 * HID * HWSZ];        // concat(hf1[-1], hr1[-1])

// ---------------- packed f32x2 helpers --------------------------------------
__device__ __forceinline__ unsigned long long pack2(float lo, float hi) {
    unsigned long long r;
    asm("mov.b64 %0, {%1, %2};" : "=l"(r) : "f"(lo), "f"(hi));
    return r;
}
__device__ __forceinline__ void unpack2(unsigned long long v, float& lo, float& hi) {
    asm("mov.b64 {%0, %1}, %2;" : "=f"(lo), "=f"(hi) : "l"(v));
}
__device__ __forceinline__ unsigned long long fma2(unsigned long long a,
                                                   unsigned long long b,
                                                   unsigned long long c) {
    unsigned long long d;
    asm("fma.rn.f32x2 %0, %1, %2, %3;" : "=l"(d) : "l"(a), "l"(b), "l"(c));
    return d;
}

// ---------------- 3x3 SAME conv, 32x32 images -------------------------------
// Tile: 32 wide x 16 tall, 128 threads (each thread: column x, 4 consecutive rows).
// OC block: 32 of 256 gate channels. Cin chunked by 8 through smem.
// MODE 0: layer-0 ih conv from `features` ([B][T][C][H][W]), both dirs in grid.z,
//         writes gates = conv + b_ih + b_hh.
// MODE 1: hh step conv, accumulates into gates[dir][t_eff][b]; dirs in grid.z.
// MODE 2: generic contiguous image list ([z][Cin][H][W]) -> gates[z], writes + biases.
constexpr int TW = 32, TH = 16, CK = 8, OCB = 32;

template <int CIN_T, int MODE>
__global__ void __launch_bounds__(128)
conv3x3_kernel(const float* __restrict__ in_base,
               const float* __restrict__ w0, const float* __restrict__ w1,
               const float* __restrict__ bih0, const float* __restrict__ bhh0,
               const float* __restrict__ bih1, const float* __restrict__ bhh1,
               float* __restrict__ out_base, int t)
{
    __shared__ float s_in[CK * 18 * 34];                    // 19.6 KB
    __shared__ __align__(16) float s_w[OCB * CK * 9 * 2];   // duplicated pairs, 18.4 KB

    const int tid = threadIdx.x;
    const int x   = tid & 31;
    const int ys4 = (tid >> 5) << 2;           // 0,4,8,12
    const int y0  = blockIdx.x * TH;           // 0 or 16
    const int oc0 = blockIdx.y * OCB;
    const int z   = blockIdx.z;

    const float* in_img;
    const float* w;
    const float* bih = bih0;
    const float* bhh = bhh0;
    float* out_img;

    if (MODE == 0) {
        int dir = z >> 6;
        int tt  = (z >> 3) & 7;
        int b   = z & 7;
        in_img  = in_base + (size_t)(b * TT + tt) * CIN_T * HWSZ;
        w       = dir ? w1 : w0;
        bih     = dir ? bih1 : bih0;
        bhh     = dir ? bhh1 : bhh0;
        out_img = out_base + (size_t)z * GG * HWSZ;
    } else if (MODE == 1) {
        int dir = z >> 3;
        int b   = z & 7;
        in_img  = in_base + (size_t)z * CIN_T * HWSZ;
        w       = dir ? w1 : w0;
        int teff = dir ? (TT - 1 - t) : t;
        out_img = out_base + (size_t)((dir * TT + teff) * BB + b) * GG * HWSZ;
    } else {
        in_img  = in_base + (size_t)z * CIN_T * HWSZ;
        w       = w0;
        out_img = out_base + (size_t)z * GG * HWSZ;
    }

    unsigned long long acc01[OCB], acc23[OCB];
#pragma unroll
    for (int oc = 0; oc < OCB; oc++) { acc01[oc] = 0ULL; acc23[oc] = 0ULL; }

    for (int cb = 0; cb < CIN_T; cb += CK) {
        __syncthreads();
        // ---- load input chunk with halo (zero-padded) ----
        const float* inp = in_img + (size_t)cb * HWSZ;
        for (int i = tid; i < CK * 18 * 34; i += 128) {
            int ci = i / (18 * 34);
            int r  = i - ci * (18 * 34);
            int yy = r / 34;
            int xx = r - yy * 34;
            int gy = y0 + yy - 1;
            int gx = xx - 1;
            float v = 0.f;
            if ((unsigned)gy < 32u && (unsigned)gx < 32u)
                v = inp[ci * HWSZ + gy * 32 + gx];
            s_in[i] = v;
        }
        // ---- load weights, duplicated into f32x2 pairs ----
        for (int i = tid; i < OCB * CK * 9; i += 128) {
            int oc = i / (CK * 9);
            int r  = i - oc * (CK * 9);   // r = ci*9 + k
            float wv = w[(size_t)(oc0 + oc) * CIN_T * 9 + (size_t)cb * 9 + r];
            s_w[(oc * (CK * 9) + r) * 2 + 0] = wv;
            s_w[(oc * (CK * 9) + r) * 2 + 1] = wv;
        }
        __syncthreads();

        // ---- compute ----
        for (int ci = 0; ci < CK; ci++) {
#pragma unroll
            for (int ky = 0; ky < 3; ky++) {
                const float* ib = s_in + ci * (18 * 34) + (ys4 + ky) * 34 + x;
                const unsigned long long* wb =
                    reinterpret_cast<const unsigned long long*>(s_w) + ci * 9 + ky * 3;
#pragma unroll
                for (int kx = 0; kx < 3; kx++) {
                    float i0 = ib[kx];
                    float i1 = ib[kx + 34];
                    float i2 = ib[kx + 68];
                    float i3 = ib[kx + 102];
                    unsigned long long p01 = pack2(i0, i1);
                    unsigned long long p23 = pack2(i2, i3);
#pragma unroll
                    for (int oc = 0; oc < OCB; oc++) {
                        unsigned long long wv = wb[oc * (CK * 9) + kx];
                        acc01[oc] = fma2(wv, p01, acc01[oc]);
                        acc23[oc] = fma2(wv, p23, acc23[oc]);
                    }
                }
            }
        }
    }

    // ---- epilogue ----
#pragma unroll 4
    for (int oc = 0; oc < OCB; oc++) {
        float a0, a1, a2, a3;
        unpack2(acc01[oc], a0, a1);
        unpack2(acc23[oc], a2, a3);
        float* op = out_img + (size_t)(oc0 + oc) * HWSZ + (y0 + ys4) * 32 + x;
        if (MODE == 1) {
            op[0]  += a0; op[32] += a1; op[64] += a2; op[96] += a3;
        } else {
            float bv = bih[oc0 + oc] + bhh[oc0 + oc];
            op[0]  = a0 + bv; op[32] = a1 + bv; op[64] = a2 + bv; op[96] = a3 + bv;
        }
    }
}

// ---------------- pointwise LSTM cell update --------------------------------
__device__ __forceinline__ float sigmoidf_(float v) { return 1.f / (1.f + expf(-v)); }

__global__ void cell_kernel(const float* __restrict__ gates,
                            float* __restrict__ h, float* __restrict__ c,
                            float* __restrict__ xs1, float* __restrict__ last,
                            int t, int zero_init, int last_choff, int ndir)
{
    int idx = blockIdx.x * blockDim.x + threadIdx.x;
    if (idx >= ndir * BB * HID * HWSZ) return;
    int px = idx & (HWSZ - 1);
    int r  = idx >> 10;
    int hc = r & (HID - 1);
    r >>= 6;
    int b   = r & 7;
    int dir = r >> 3;
    int teff = dir ? (TT - 1 - t) : t;

    size_t gb = ((size_t)((dir * TT + teff) * BB + b) * GG) * HWSZ + px;
    float gi = gates[gb + (size_t)hc * HWSZ];
    float gf = gates[gb + (size_t)(hc + HID) * HWSZ];
    float gg = gates[gb + (size_t)(hc + 2 * HID) * HWSZ];
    float go = gates[gb + (size_t)(hc + 3 * HID) * HWSZ];

    float cp = zero_init ? 0.f : c[idx];
    float cn = sigmoidf_(gf) * cp + sigmoidf_(gi) * tanhf(gg);
    float hn = sigmoidf_(go) * tanhf(cn);
    c[idx] = cn;
    h[idx] = hn;
    if (xs1)
        xs1[(((size_t)teff * BB + b) * (2 * HID) + dir * HID + hc) * HWSZ + px] = hn;
    if (last)
        last[((size_t)b * (2 * HID) + last_choff + hc) * HWSZ + px] = hn;
}

// ---------------- 1x1 conv + ReLU head --------------------------------------
__global__ void conv1x1_relu_kernel(const float* __restrict__ last,
                                    const float* __restrict__ w,
                                    const float* __restrict__ bias,
                                    float* __restrict__ out)
{
    int idx = blockIdx.x * 256 + threadIdx.x;   // B*OUTC*HWSZ = 524288
    int px = idx & 1023;
    int o  = (idx >> 10) & 63;
    int b  = idx >> 16;
    const float* lp = last + (size_t)b * 2 * HID * HWSZ + px;
    const float* wp = w + o * 2 * HID;
    float s = bias[o];
#pragma unroll 8
    for (int cc = 0; cc < 2 * HID; cc++)
        s += lp[(size_t)cc * HWSZ] * wp[cc];
    out[idx] = fmaxf(s, 0.f);
}

// ---------------- host orchestration ----------------------------------------
extern "C" void kernel_launch(void* const* d_in, const int* in_sizes, int n_in,
                              void* d_out, int out_size)
{
    const float* features = (const float*)d_in[0];
    const float* w_ih0f = (const float*)d_in[1];
    const float* w_hh0f = (const float*)d_in[2];
    const float* b_ih0f = (const float*)d_in[3];
    const float* b_hh0f = (const float*)d_in[4];
    const float* w_ih0r = (const float*)d_in[5];
    const float* w_hh0r = (const float*)d_in[6];
    const float* b_ih0r = (const float*)d_in[7];
    const float* b_hh0r = (const float*)d_in[8];
    const float* w_ih1f = (const float*)d_in[9];
    const float* w_hh1f = (const float*)d_in[10];
    const float* b_ih1f = (const float*)d_in[11];
    const float* b_hh1f = (const float*)d_in[12];
    const float* w_ih1r = (const float*)d_in[13];
    const float* w_hh1r = (const float*)d_in[14];
    const float* b_ih1r = (const float*)d_in[15];
    const float* b_hh1r = (const float*)d_in[16];
    const float* w_out  = (const float*)d_in[17];
    const float* b_out  = (const float*)d_in[18];
    float* out = (float*)d_out;

    float *gates, *xs1, *h, *c, *last;
    cudaGetSymbolAddress((void**)&gates, g_gates);
    cudaGetSymbolAddress((void**)&xs1,   g_xs1);
    cudaGetSymbolAddress((void**)&h,     g_h);
    cudaGetSymbolAddress((void**)&c,     g_c);
    cudaGetSymbolAddress((void**)&last,  g_last);

    dim3 blk(128);
    const int cell2 = (2 * BB * HID * HWSZ) / 256;   // both dirs
    const int cell1 = (BB * HID * HWSZ) / 256;       // one dir

    // ===== Layer 0: ih gates for all (dir, t) in one launch (biases folded) =====
    conv3x3_kernel<CINC, 0><<<dim3(2, 8, 2 * TT * BB), blk>>>(
        features, w_ih0f, w_ih0r, b_ih0f, b_hh0f, b_ih0r, b_hh0r, gates, 0);

    // t = 0: h=c=0 so conv_hh contributes nothing (biases already folded)
    cell_kernel<<<cell2, 256>>>(gates, h, c, xs1, nullptr, 0, 1, 0, 2);
    for (int t = 1; t < TT; t++) {
        conv3x3_kernel<HID, 1><<<dim3(2, 8, 2 * BB), blk>>>(
            h, w_hh0f, w_hh0r, nullptr, nullptr, nullptr, nullptr, gates, t);
        cell_kernel<<<cell2, 256>>>(gates, h, c, xs1, nullptr, t, 0, 0, 2);
    }

    // ===== Layer 1 reverse: only hr1[T-1] is needed (single step, h0=0) =====
    float* gates_rev = gates + (size_t)TT * BB * GG * HWSZ;
    conv3x3_kernel<CINC, 2><<<dim3(2, 8, BB), blk>>>(
        xs1 + (size_t)(TT - 1) * BB * 2 * HID * HWSZ,
        w_ih1r, nullptr, b_ih1r, b_hh1r, nullptr, nullptr, gates_rev, 0);
    cell_kernel<<<cell1, 256>>>(gates_rev,
                                h + (size_t)BB * HID * HWSZ,   // scratch region
                                c + (size_t)BB * HID * HWSZ,
                                nullptr, last, 0, 1, HID, 1);

    // ===== Layer 1 forward =====
    conv3x3_kernel<CINC, 2><<<dim3(2, 8, TT * BB), blk>>>(
        xs1, w_ih1f, nullptr, b_ih1f, b_hh1f, nullptr, nullptr, gates, 0);
    cell_kernel<<<cell1, 256>>>(gates, h, c, nullptr, nullptr, 0, 1, 0, 1);
    for (int t = 1; t < TT; t++) {
        conv3x3_kernel<HID, 1><<<dim3(2, 8, BB), blk>>>(
            h, w_hh1f, nullptr, nullptr, nullptr, nullptr, nullptr, gates, t);
        cell_kernel<<<cell1, 256>>>(gates, h, c, nullptr,
                                    (t == TT - 1) ? last : nullptr, t, 0, 0, 1);
    }

    // ===== 1x1 conv + ReLU =====
    conv1x1_relu_kernel<<<(BB * OUTC * HWSZ) / 256, 256>>>(last, w_out, b_out, out);
}

// round 3
// speedup vs baseline: 1.0449x; 1.0449x over previous
#include <cuda_runtime.h>
#include <cstdint>
#include <cstdio>

#define TT 8
#define BB 8
#define CINC 128
#define HID 64
#define GG 256      // 4*HID gate channels
#define HWSZ 1024   // 32*32
#define OUTC 64

// ---------------- scratch (device globals; no allocations allowed) ----------
__device__ float g_gates[(size_t)2 * TT * BB * GG * HWSZ];   // [dir][t][b][256][1024] (134MB)
__device__ float g_xs1[(size_t)TT * BB * 2 * HID * HWSZ];    // layer-1 input  [t][b][128][1024]
__device__ float g_h[(size_t)2 * BB * HID * HWSZ];           // [dir][b][64][1024]
__device__ float g_c[(size_t)2 * BB * HID * HWSZ];
__device__ float g_last[(size_t)BB * 2 * HID * HWSZ];        // concat(hf1[-1], hr1[-1])

// ---------------- packed f32x2 helpers --------------------------------------
__device__ __forceinline__ unsigned long long pack2(float lo, float hi) {
    unsigned long long r;
    asm("mov.b64 %0, {%1, %2};" : "=l"(r) : "f"(lo), "f"(hi));
    return r;
}
__device__ __forceinline__ void unpack2(unsigned long long v, float& lo, float& hi) {
    asm("mov.b64 {%0, %1}, %2;" : "=f"(lo), "=f"(hi) : "l"(v));
}
__device__ __forceinline__ unsigned long long fma2(unsigned long long a,
                                                   unsigned long long b,
                                                   unsigned long long c) {
    unsigned long long d;
    asm("fma.rn.f32x2 %0, %1, %2, %3;" : "=l"(d) : "l"(a), "l"(b), "l"(c));
    return d;
}

// ---------------- 3x3 SAME conv, 32x32 images -------------------------------
// Tile: 32 wide x 16 tall, 128 threads (each thread: column x, 4 consecutive rows).
// OC block: 32 of 256 gate channels. Cin chunked by 8 through smem.
// MODE 0: layer-0 ih conv from `features` ([B][T][C][H][W]), both dirs in grid.z,
//         writes gates = conv + b_ih + b_hh.
// MODE 1: hh step conv, accumulates into gates[dir][t_eff][b]; dirs in grid.z.
// MODE 2: generic contiguous image list ([z][Cin][H][W]) -> gates[z], writes + biases.
constexpr int TW = 32, TH = 16, CK = 8, OCB = 32;

template <int CIN_T, int MODE>
__global__ void __launch_bounds__(128)
conv3x3_kernel(const float* __restrict__ in_base,
               const float* __restrict__ w0, const float* __restrict__ w1,
               const float* __restrict__ bih0, const float* __restrict__ bhh0,
               const float* __restrict__ bih1, const float* __restrict__ bhh1,
               float* __restrict__ out_base, int t)
{
    __shared__ float s_in[CK * 18 * 34];                    // 19.6 KB
    __shared__ __align__(16) float s_w[OCB * CK * 9 * 2];   // duplicated pairs, 18.4 KB

    const int tid = threadIdx.x;
    const int x   = tid & 31;
    const int ys4 = (tid >> 5) << 2;           // 0,4,8,12
    const int y0  = blockIdx.x * TH;           // 0 or 16
    const int oc0 = blockIdx.y * OCB;
    const int z   = blockIdx.z;

    const float* in_img;
    const float* w;
    const float* bih = bih0;
    const float* bhh = bhh0;
    float* out_img;

    if (MODE == 0) {
        int dir = z >> 6;
        int tt  = (z >> 3) & 7;
        int b   = z & 7;
        in_img  = in_base + (size_t)(b * TT + tt) * CIN_T * HWSZ;
        w       = dir ? w1 : w0;
        bih     = dir ? bih1 : bih0;
        bhh     = dir ? bhh1 : bhh0;
        out_img = out_base + (size_t)z * GG * HWSZ;
    } else if (MODE == 1) {
        int dir = z >> 3;
        int b   = z & 7;
        in_img  = in_base + (size_t)z * CIN_T * HWSZ;
        w       = dir ? w1 : w0;
        int teff = dir ? (TT - 1 - t) : t;
        out_img = out_base + (size_t)((dir * TT + teff) * BB + b) * GG * HWSZ;
    } else {
        in_img  = in_base + (size_t)z * CIN_T * HWSZ;
        w       = w0;
        out_img = out_base + (size_t)z * GG * HWSZ;
    }

    unsigned long long acc01[OCB], acc23[OCB];
#pragma unroll
    for (int oc = 0; oc < OCB; oc++) { acc01[oc] = 0ULL; acc23[oc] = 0ULL; }

    for (int cb = 0; cb < CIN_T; cb += CK) {
        __syncthreads();
        // ---- load input chunk with halo (zero-padded) ----
        const float* inp = in_img + (size_t)cb * HWSZ;
        for (int i = tid; i < CK * 18 * 34; i += 128) {
            int ci = i / (18 * 34);
            int r  = i - ci * (18 * 34);
            int yy = r / 34;
            int xx = r - yy * 34;
            int gy = y0 + yy - 1;
            int gx = xx - 1;
            float v = 0.f;
            if ((unsigned)gy < 32u && (unsigned)gx < 32u)
                v = inp[ci * HWSZ + gy * 32 + gx];
            s_in[i] = v;
        }
        // ---- load weights, duplicated into f32x2 pairs ----
        for (int i = tid; i < OCB * CK * 9; i += 128) {
            int oc = i / (CK * 9);
            int r  = i - oc * (CK * 9);   // r = ci*9 + k
            float wv = w[(size_t)(oc0 + oc) * CIN_T * 9 + (size_t)cb * 9 + r];
            s_w[(oc * (CK * 9) + r) * 2 + 0] = wv;
            s_w[(oc * (CK * 9) + r) * 2 + 1] = wv;
        }
        __syncthreads();

        // ---- compute ----
        for (int ci = 0; ci < CK; ci++) {
#pragma unroll
            for (int ky = 0; ky < 3; ky++) {
                const float* ib = s_in + ci * (18 * 34) + (ys4 + ky) * 34 + x;
                const unsigned long long* wb =
                    reinterpret_cast<const unsigned long long*>(s_w) + ci * 9 + ky * 3;
#pragma unroll
                for (int kx = 0; kx < 3; kx++) {
                    float i0 = ib[kx];
                    float i1 = ib[kx + 34];
                    float i2 = ib[kx + 68];
                    float i3 = ib[kx + 102];
                    unsigned long long p01 = pack2(i0, i1);
                    unsigned long long p23 = pack2(i2, i3);
#pragma unroll
                    for (int oc = 0; oc < OCB; oc++) {
                        unsigned long long wv = wb[oc * (CK * 9) + kx];
                        acc01[oc] = fma2(wv, p01, acc01[oc]);
                        acc23[oc] = fma2(wv, p23, acc23[oc]);
                    }
                }
            }
        }
    }

    // ---- epilogue ----
#pragma unroll 4
    for (int oc = 0; oc < OCB; oc++) {
        float a0, a1, a2, a3;
        unpack2(acc01[oc], a0, a1);
        unpack2(acc23[oc], a2, a3);
        float* op = out_img + (size_t)(oc0 + oc) * HWSZ + (y0 + ys4) * 32 + x;
        if (MODE == 1) {
            op[0]  += a0; op[32] += a1; op[64] += a2; op[96] += a3;
        } else {
            float bv = bih[oc0 + oc] + bhh[oc0 + oc];
            op[0]  = a0 + bv; op[32] = a1 + bv; op[64] = a2 + bv; op[96] = a3 + bv;
        }
    }
}

// ---------------- pointwise LSTM cell update --------------------------------
__device__ __forceinline__ float sigmoidf_(float v) { return 1.f / (1.f + expf(-v)); }

__global__ void cell_kernel(const float* __restrict__ gates,
                            float* __restrict__ h, float* __restrict__ c,
                            float* __restrict__ xs1, float* __restrict__ last,
                            int t, int zero_init, int last_choff, int ndir)
{
    int idx = blockIdx.x * blockDim.x + threadIdx.x;
    if (idx >= ndir * BB * HID * HWSZ) return;
    int px = idx & (HWSZ - 1);
    int r  = idx >> 10;
    int hc = r & (HID - 1);
    r >>= 6;
    int b   = r & 7;
    int dir = r >> 3;
    int teff = dir ? (TT - 1 - t) : t;

    size_t gb = ((size_t)((dir * TT + teff) * BB + b) * GG) * HWSZ + px;
    float gi = gates[gb + (size_t)hc * HWSZ];
    float gf = gates[gb + (size_t)(hc + HID) * HWSZ];
    float gg = gates[gb + (size_t)(hc + 2 * HID) * HWSZ];
    float go = gates[gb + (size_t)(hc + 3 * HID) * HWSZ];

    float cp = zero_init ? 0.f : c[idx];
    float cn = sigmoidf_(gf) * cp + sigmoidf_(gi) * tanhf(gg);
    float hn = sigmoidf_(go) * tanhf(cn);
    c[idx] = cn;
    h[idx] = hn;
    if (xs1)
        xs1[(((size_t)teff * BB + b) * (2 * HID) + dir * HID + hc) * HWSZ + px] = hn;
    if (last)
        last[((size_t)b * (2 * HID) + last_choff + hc) * HWSZ + px] = hn;
}

// ---------------- 1x1 conv + ReLU head --------------------------------------
__global__ void conv1x1_relu_kernel(const float* __restrict__ last,
                                    const float* __restrict__ w,
                                    const float* __restrict__ bias,
                                    float* __restrict__ out)
{
    int idx = blockIdx.x * 256 + threadIdx.x;   // B*OUTC*HWSZ = 524288
    int px = idx & 1023;
    int o  = (idx >> 10) & 63;
    int b  = idx >> 16;
    const float* lp = last + (size_t)b * 2 * HID * HWSZ + px;
    const float* wp = w + o * 2 * HID;
    float s = bias[o];
#pragma unroll 8
    for (int cc = 0; cc < 2 * HID; cc++)
        s += lp[(size_t)cc * HWSZ] * wp[cc];
    out[idx] = fmaxf(s, 0.f);
}

// ---------------- host orchestration ----------------------------------------
extern "C" void kernel_launch(void* const* d_in, const int* in_sizes, int n_in,
                              void* d_out, int out_size)
{
    const float* features = (const float*)d_in[0];
    const float* w_ih0f = (const float*)d_in[1];
    const float* w_hh0f = (const float*)d_in[2];
    const float* b_ih0f = (const float*)d_in[3];
    const float* b_hh0f = (const float*)d_in[4];
    const float* w_ih0r = (const float*)d_in[5];
    const float* w_hh0r = (const float*)d_in[6];
    const float* b_ih0r = (const float*)d_in[7];
    const float* b_hh0r = (const float*)d_in[8];
    const float* w_ih1f = (const float*)d_in[9];
    const float* w_hh1f = (const float*)d_in[10];
    const float* b_ih1f = (const float*)d_in[11];
    const float* b_hh1f = (const float*)d_in[12];
    const float* w_ih1r = (const float*)d_in[13];
    const float* w_hh1r = (const float*)d_in[14];
    const float* b_ih1r = (const float*)d_in[15];
    const float* b_hh1r = (const float*)d_in[16];
    const float* w_out  = (const float*)d_in[17];
    const float* b_out  = (const float*)d_in[18];
    float* out = (float*)d_out;

    float *gates, *xs1, *h, *c, *last;
    cudaGetSymbolAddress((void**)&gates, g_gates);
    cudaGetSymbolAddress((void**)&xs1,   g_xs1);
    cudaGetSymbolAddress((void**)&h,     g_h);
    cudaGetSymbolAddress((void**)&c,     g_c);
    cudaGetSymbolAddress((void**)&last,  g_last);

    dim3 blk(128);
    const int cell2 = (2 * BB * HID * HWSZ) / 256;   // both dirs
    const int cell1 = (BB * HID * HWSZ) / 256;       // one dir

    // ===== Layer 0: ih gates for all (dir, t) in one launch (biases folded) =====
    conv3x3_kernel<CINC, 0><<<dim3(2, 8, 2 * TT * BB), blk>>>(
        features, w_ih0f, w_ih0r, b_ih0f, b_hh0f, b_ih0r, b_hh0r, gates, 0);

    // t = 0: h=c=0 so conv_hh contributes nothing (biases already folded)
    cell_kernel<<<cell2, 256>>>(gates, h, c, xs1, nullptr, 0, 1, 0, 2);
    for (int t = 1; t < TT; t++) {
        conv3x3_kernel<HID, 1><<<dim3(2, 8, 2 * BB), blk>>>(
            h, w_hh0f, w_hh0r, nullptr, nullptr, nullptr, nullptr, gates, t);
        cell_kernel<<<cell2, 256>>>(gates, h, c, xs1, nullptr, t, 0, 0, 2);
    }

    // ===== Layer 1 reverse: only hr1[T-1] is needed (single step, h0=0) =====
    float* gates_rev = gates + (size_t)TT * BB * GG * HWSZ;
    conv3x3_kernel<CINC, 2><<<dim3(2, 8, BB), blk>>>(
        xs1 + (size_t)(TT - 1) * BB * 2 * HID * HWSZ,
        w_ih1r, nullptr, b_ih1r, b_hh1r, nullptr, nullptr, gates_rev, 0);
    cell_kernel<<<cell1, 256>>>(gates_rev,
                                h + (size_t)BB * HID * HWSZ,   // scratch region
                                c + (size_t)BB * HID * HWSZ,
                                nullptr, last, 0, 1, HID, 1);

    // ===== Layer 1 forward =====
    conv3x3_kernel<CINC, 2><<<dim3(2, 8, TT * BB), blk>>>(
        xs1, w_ih1f, nullptr, b_ih1f, b_hh1f, nullptr, nullptr, gates, 0);
    cell_kernel<<<cell1, 256>>>(gates, h, c, nullptr, nullptr, 0, 1, 0, 1);
    for (int t = 1; t < TT; t++) {
        conv3x3_kernel<HID, 1><<<dim3(2, 8, BB), blk>>>(
            h, w_hh1f, nullptr, nullptr, nullptr, nullptr, nullptr, gates, t);
        cell_kernel<<<cell1, 256>>>(gates, h, c, nullptr,
                                    (t == TT - 1) ? last : nullptr, t, 0, 0, 1);
    }

    // ===== 1x1 conv + ReLU =====
    conv1x1_relu_kernel<<<(BB * OUTC * HWSZ) / 256, 256>>>(last, w_out, b_out, out);
}

// round 4
// speedup vs baseline: 1.0468x; 1.0018x over previous
#include <cuda_runtime.h>
#include <cstdint>
#include <cstdio>

#define TT 8
#define BB 8
#define CINC 128
#define HID 64
#define GG 256      // 4*HID gate channels
#define HWSZ 1024   // 32*32
#define OUTC 64

// ---------------- scratch (device globals; no allocations allowed) ----------
__device__ float g_gates[(size_t)2 * TT * BB * GG * HWSZ];   // [dir][t][b][256][1024] (134MB)
__device__ float g_xs1[(size_t)TT * BB * 2 * HID * HWSZ];    // layer-1 input  [t][b][128][1024]
__device__ float g_h[(size_t)2 * BB * HID * HWSZ];           // [dir][b][64][1024]
__device__ float g_c[(size_t)2 * BB * HID * HWSZ];
__device__ float g_last[(size_t)BB * 2 * HID * HWSZ];        // concat(hf1[-1], hr1[-1])

// ---------------- packed f32x2 helpers --------------------------------------
__device__ __forceinline__ unsigned long long pack2(float lo, float hi) {
    unsigned long long r;
    asm("mov.b64 %0, {%1, %2};" : "=l"(r) : "f"(lo), "f"(hi));
    return r;
}
__device__ __forceinline__ void unpack2(unsigned long long v, float& lo, float& hi) {
    asm("mov.b64 {%0, %1}, %2;" : "=f"(lo), "=f"(hi) : "l"(v));
}
__device__ __forceinline__ unsigned long long fma2(unsigned long long a,
                                                   unsigned long long b,
                                                   unsigned long long c) {
    unsigned long long d;
    asm("fma.rn.f32x2 %0, %1, %2, %3;" : "=l"(d) : "l"(a), "l"(b), "l"(c));
    return d;
}

// ---------------- 3x3 SAME conv, 32x32 images -------------------------------
// Tile: 32 wide x 16 tall, 128 threads (each thread: column x, 4 consecutive rows).
// OC block: 32 of 256 gate channels. Cin chunked by 8 through smem.
// MODE 0: layer-0 ih conv from `features` ([B][T][C][H][W]), both dirs in grid.z,
//         writes gates = conv + b_ih + b_hh.
// MODE 1: hh step conv, accumulates into gates[dir][t_eff][b]; dirs in grid.z.
// MODE 2: generic contiguous image list ([z][Cin][H][W]) -> gates[z], writes + biases.
constexpr int TW = 32, TH = 16, CK = 8, OCB = 32;

template <int CIN_T, int MODE>
__global__ void __launch_bounds__(128)
conv3x3_kernel(const float* __restrict__ in_base,
               const float* __restrict__ w0, const float* __restrict__ w1,
               const float* __restrict__ bih0, const float* __restrict__ bhh0,
               const float* __restrict__ bih1, const float* __restrict__ bhh1,
               float* __restrict__ out_base, int t)
{
    __shared__ float s_in[CK * 18 * 34];                    // 19.6 KB
    __shared__ __align__(16) float s_w[OCB * CK * 9 * 2];   // duplicated pairs, 18.4 KB

    const int tid = threadIdx.x;
    const int x   = tid & 31;
    const int ys4 = (tid >> 5) << 2;           // 0,4,8,12
    const int y0  = blockIdx.x * TH;           // 0 or 16
    const int oc0 = blockIdx.y * OCB;
    const int z   = blockIdx.z;

    const float* in_img;
    const float* w;
    const float* bih = bih0;
    const float* bhh = bhh0;
    float* out_img;

    if (MODE == 0) {
        int dir = z >> 6;
        int tt  = (z >> 3) & 7;
        int b   = z & 7;
        in_img  = in_base + (size_t)(b * TT + tt) * CIN_T * HWSZ;
        w       = dir ? w1 : w0;
        bih     = dir ? bih1 : bih0;
        bhh     = dir ? bhh1 : bhh0;
        out_img = out_base + (size_t)z * GG * HWSZ;
    } else if (MODE == 1) {
        int dir = z >> 3;
        int b   = z & 7;
        in_img  = in_base + (size_t)z * CIN_T * HWSZ;
        w       = dir ? w1 : w0;
        int teff = dir ? (TT - 1 - t) : t;
        out_img = out_base + (size_t)((dir * TT + teff) * BB + b) * GG * HWSZ;
    } else {
        in_img  = in_base + (size_t)z * CIN_T * HWSZ;
        w       = w0;
        out_img = out_base + (size_t)z * GG * HWSZ;
    }

    unsigned long long acc01[OCB], acc23[OCB];
#pragma unroll
    for (int oc = 0; oc < OCB; oc++) { acc01[oc] = 0ULL; acc23[oc] = 0ULL; }

    for (int cb = 0; cb < CIN_T; cb += CK) {
        __syncthreads();
        // ---- load input chunk with halo (zero-padded) ----
        const float* inp = in_img + (size_t)cb * HWSZ;
        for (int i = tid; i < CK * 18 * 34; i += 128) {
            int ci = i / (18 * 34);
            int r  = i - ci * (18 * 34);
            int yy = r / 34;
            int xx = r - yy * 34;
            int gy = y0 + yy - 1;
            int gx = xx - 1;
            float v = 0.f;
            if ((unsigned)gy < 32u && (unsigned)gx < 32u)
                v = inp[ci * HWSZ + gy * 32 + gx];
            s_in[i] = v;
        }
        // ---- load weights, duplicated into f32x2 pairs ----
        for (int i = tid; i < OCB * CK * 9; i += 128) {
            int oc = i / (CK * 9);
            int r  = i - oc * (CK * 9);   // r = ci*9 + k
            float wv = w[(size_t)(oc0 + oc) * CIN_T * 9 + (size_t)cb * 9 + r];
            s_w[(oc * (CK * 9) + r) * 2 + 0] = wv;
            s_w[(oc * (CK * 9) + r) * 2 + 1] = wv;
        }
        __syncthreads();

        // ---- compute ----
        for (int ci = 0; ci < CK; ci++) {
#pragma unroll
            for (int ky = 0; ky < 3; ky++) {
                const float* ib = s_in + ci * (18 * 34) + (ys4 + ky) * 34 + x;
                const unsigned long long* wb =
                    reinterpret_cast<const unsigned long long*>(s_w) + ci * 9 + ky * 3;
#pragma unroll
                for (int kx = 0; kx < 3; kx++) {
                    float i0 = ib[kx];
                    float i1 = ib[kx + 34];
                    float i2 = ib[kx + 68];
                    float i3 = ib[kx + 102];
                    unsigned long long p01 = pack2(i0, i1);
                    unsigned long long p23 = pack2(i2, i3);
#pragma unroll
                    for (int oc = 0; oc < OCB; oc++) {
                        unsigned long long wv = wb[oc * (CK * 9) + kx];
                        acc01[oc] = fma2(wv, p01, acc01[oc]);
                        acc23[oc] = fma2(wv, p23, acc23[oc]);
                    }
                }
            }
        }
    }

    // ---- epilogue ----
#pragma unroll 4
    for (int oc = 0; oc < OCB; oc++) {
        float a0, a1, a2, a3;
        unpack2(acc01[oc], a0, a1);
        unpack2(acc23[oc], a2, a3);
        float* op = out_img + (size_t)(oc0 + oc) * HWSZ + (y0 + ys4) * 32 + x;
        if (MODE == 1) {
            op[0]  += a0; op[32] += a1; op[64] += a2; op[96] += a3;
        } else {
            float bv = bih[oc0 + oc] + bhh[oc0 + oc];
            op[0]  = a0 + bv; op[32] = a1 + bv; op[64] = a2 + bv; op[96] = a3 + bv;
        }
    }
}

// ---------------- pointwise LSTM cell update --------------------------------
__device__ __forceinline__ float sigmoidf_(float v) { return 1.f / (1.f + expf(-v)); }

__global__ void cell_kernel(const float* __restrict__ gates,
                            float* __restrict__ h, float* __restrict__ c,
                            float* __restrict__ xs1, float* __restrict__ last,
                            int t, int zero_init, int last_choff, int ndir)
{
    int idx = blockIdx.x * blockDim.x + threadIdx.x;
    if (idx >= ndir * BB * HID * HWSZ) return;
    int px = idx & (HWSZ - 1);
    int r  = idx >> 10;
    int hc = r & (HID - 1);
    r >>= 6;
    int b   = r & 7;
    int dir = r >> 3;
    int teff = dir ? (TT - 1 - t) : t;

    size_t gb = ((size_t)((dir * TT + teff) * BB + b) * GG) * HWSZ + px;
    float gi = gates[gb + (size_t)hc * HWSZ];
    float gf = gates[gb + (size_t)(hc + HID) * HWSZ];
    float gg = gates[gb + (size_t)(hc + 2 * HID) * HWSZ];
    float go = gates[gb + (size_t)(hc + 3 * HID) * HWSZ];

    float cp = zero_init ? 0.f : c[idx];
    float cn = sigmoidf_(gf) * cp + sigmoidf_(gi) * tanhf(gg);
    float hn = sigmoidf_(go) * tanhf(cn);
    c[idx] = cn;
    h[idx] = hn;
    if (xs1)
        xs1[(((size_t)teff * BB + b) * (2 * HID) + dir * HID + hc) * HWSZ + px] = hn;
    if (last)
        last[((size_t)b * (2 * HID) + last_choff + hc) * HWSZ + px] = hn;
}

// ---------------- 1x1 conv + ReLU head --------------------------------------
__global__ void conv1x1_relu_kernel(const float* __restrict__ last,
                                    const float* __restrict__ w,
                                    const float* __restrict__ bias,
                                    float* __restrict__ out)
{
    int idx = blockIdx.x * 256 + threadIdx.x;   // B*OUTC*HWSZ = 524288
    int px = idx & 1023;
    int o  = (idx >> 10) & 63;
    int b  = idx >> 16;
    const float* lp = last + (size_t)b * 2 * HID * HWSZ + px;
    const float* wp = w + o * 2 * HID;
    float s = bias[o];
#pragma unroll 8
    for (int cc = 0; cc < 2 * HID; cc++)
        s += lp[(size_t)cc * HWSZ] * wp[cc];
    out[idx] = fmaxf(s, 0.f);
}

// ---------------- host orchestration ----------------------------------------
extern "C" void kernel_launch(void* const* d_in, const int* in_sizes, int n_in,
                              void* d_out, int out_size)
{
    const float* features = (const float*)d_in[0];
    const float* w_ih0f = (const float*)d_in[1];
    const float* w_hh0f = (const float*)d_in[2];
    const float* b_ih0f = (const float*)d_in[3];
    const float* b_hh0f = (const float*)d_in[4];
    const float* w_ih0r = (const float*)d_in[5];
    const float* w_hh0r = (const float*)d_in[6];
    const float* b_ih0r = (const float*)d_in[7];
    const float* b_hh0r = (const float*)d_in[8];
    const float* w_ih1f = (const float*)d_in[9];
    const float* w_hh1f = (const float*)d_in[10];
    const float* b_ih1f = (const float*)d_in[11];
    const float* b_hh1f = (const float*)d_in[12];
    const float* w_ih1r = (const float*)d_in[13];
    const float* w_hh1r = (const float*)d_in[14];
    const float* b_ih1r = (const float*)d_in[15];
    const float* b_hh1r = (const float*)d_in[16];
    const float* w_out  = (const float*)d_in[17];
    const float* b_out  = (const float*)d_in[18];
    float* out = (float*)d_out;

    float *gates, *xs1, *h, *c, *last;
    cudaGetSymbolAddress((void**)&gates, g_gates);
    cudaGetSymbolAddress((void**)&xs1,   g_xs1);
    cudaGetSymbolAddress((void**)&h,     g_h);
    cudaGetSymbolAddress((void**)&c,     g_c);
    cudaGetSymbolAddress((void**)&last,  g_last);

    dim3 blk(128);
    const int cell2 = (2 * BB * HID * HWSZ) / 256;   // both dirs
    const int cell1 = (BB * HID * HWSZ) / 256;       // one dir

    // ===== Layer 0: ih gates for all (dir, t) in one launch (biases folded) =====
    conv3x3_kernel<CINC, 0><<<dim3(2, 8, 2 * TT * BB), blk>>>(
        features, w_ih0f, w_ih0r, b_ih0f, b_hh0f, b_ih0r, b_hh0r, gates, 0);

    // t = 0: h=c=0 so conv_hh contributes nothing (biases already folded)
    cell_kernel<<<cell2, 256>>>(gates, h, c, xs1, nullptr, 0, 1, 0, 2);
    for (int t = 1; t < TT; t++) {
        conv3x3_kernel<HID, 1><<<dim3(2, 8, 2 * BB), blk>>>(
            h, w_hh0f, w_hh0r, nullptr, nullptr, nullptr, nullptr, gates, t);
        cell_kernel<<<cell2, 256>>>(gates, h, c, xs1, nullptr, t, 0, 0, 2);
    }

    // ===== Layer 1 reverse: only hr1[T-1] is needed (single step, h0=0) =====
    float* gates_rev = gates + (size_t)TT * BB * GG * HWSZ;
    conv3x3_kernel<CINC, 2><<<dim3(2, 8, BB), blk>>>(
        xs1 + (size_t)(TT - 1) * BB * 2 * HID * HWSZ,
        w_ih1r, nullptr, b_ih1r, b_hh1r, nullptr, nullptr, gates_rev, 0);
    cell_kernel<<<cell1, 256>>>(gates_rev,
                                h + (size_t)BB * HID * HWSZ,   // scratch region
                                c + (size_t)BB * HID * HWSZ,
                                nullptr, last, 0, 1, HID, 1);

    // ===== Layer 1 forward =====
    conv3x3_kernel<CINC, 2><<<dim3(2, 8, TT * BB), blk>>>(
        xs1, w_ih1f, nullptr, b_ih1f, b_hh1f, nullptr, nullptr, gates, 0);
    cell_kernel<<<cell1, 256>>>(gates, h, c, nullptr, nullptr, 0, 1, 0, 1);
    for (int t = 1; t < TT; t++) {
        conv3x3_kernel<HID, 1><<<dim3(2, 8, BB), blk>>>(
            h, w_hh1f, nullptr, nullptr, nullptr, nullptr, nullptr, gates, t);
        cell_kernel<<<cell1, 256>>>(gates, h, c, nullptr,
                                    (t == TT - 1) ? last : nullptr, t, 0, 0, 1);
    }

    // ===== 1x1 conv + ReLU =====
    conv1x1_relu_kernel<<<(BB * OUTC * HWSZ) / 256, 256>>>(last, w_out, b_out, out);
}

// round 7
// speedup vs baseline: 2.7992x; 2.6740x over previous
#include <cuda_runtime.h>
#include <cuda_bf16.h>
#include <cstdint>

#define TT 8
#define PX 1024
typedef __nv_bfloat16 bf16;

// ---- scratch globals ---------------------------------------------------------
__device__ __align__(16) bf16  g_ft[(size_t)64 * 2 * PX * 128];
__device__ __align__(16) bf16  g_xs1[(size_t)64 * 2 * PX * 128];
__device__ __align__(16) bf16  g_hb[(size_t)32 * 2 * PX * 64];
__device__ __align__(16) float g_cb[(size_t)32 * PX * 64];
__device__ __align__(16) float g_g0[(size_t)128 * PX * 256];
__device__ __align__(16) float g_g1[(size_t)72 * PX * 256];
__device__ __align__(16) float g_ghh[(size_t)16 * PX * 256];
__device__ __align__(16) float g_lastb[(size_t)8 * PX * 128];
__device__ __align__(16) bf16  g_wpk[(size_t)4 * 589824 + (size_t)3 * 294912];
__device__ __align__(16) float g_bc[4 * 256];

// ---- helpers ------------------------------------------------------------------
__device__ __forceinline__ uint32_t smem_u32(const void* p) {
    uint32_t a;
    asm("{ .reg .u64 t; cvta.to.shared.u64 t, %1; cvt.u32.u64 %0, t; }" : "=r"(a) : "l"(p));
    return a;
}
__device__ __forceinline__ void ldsm4(uint32_t* r, uint32_t a) {
    asm volatile("ldmatrix.sync.aligned.m8n8.x4.shared.b16 {%0,%1,%2,%3}, [%4];"
        : "=r"(r[0]), "=r"(r[1]), "=r"(r[2]), "=r"(r[3]) : "r"(a));
}
__device__ __forceinline__ void mma16816(float* d, const uint32_t* a, const uint32_t* b) {
    asm volatile("mma.sync.aligned.m16n8k16.row.col.f32.bf16.bf16.f32 "
        "{%0,%1,%2,%3},{%4,%5,%6,%7},{%8,%9},{%0,%1,%2,%3};"
        : "+f"(d[0]), "+f"(d[1]), "+f"(d[2]), "+f"(d[3])
        : "r"(a[0]), "r"(a[1]), "r"(a[2]), "r"(a[3]), "r"(b[0]), "r"(b[1]));
}
__device__ __forceinline__ void cp16(uint32_t d, const void* s, uint32_t sz) {
    asm volatile("cp.async.ca.shared.global [%0], [%1], 16, %2;" :: "r"(d), "l"(s), "r"(sz) : "memory");
}
__device__ __forceinline__ void cp16f(uint32_t d, const void* s) {
    asm volatile("cp.async.ca.shared.global [%0], [%1], 16;" :: "r"(d), "l"(s) : "memory");
}
__device__ __forceinline__ void cp_commit() { asm volatile("cp.async.commit_group;" ::: "memory"); }
__device__ __forceinline__ void cp_wait0() { asm volatile("cp.async.wait_group 0;" ::: "memory"); }
__device__ __forceinline__ void cp_wait1() { asm volatile("cp.async.wait_group 1;" ::: "memory"); }
__device__ __forceinline__ float sigf(float x) { return 1.f / (1.f + __expf(-x)); }

// ---- weight repack: fp32 [G][Cin][3][3] -> bf16 hi|lo planes [k][g][ci] -------
__global__ void repack_k(const float* __restrict__ w, const float* __restrict__ ba,
                         const float* __restrict__ bb, bf16* __restrict__ dst,
                         float* __restrict__ bc, int cin)
{
    int idx = blockIdx.x * 256 + threadIdx.x;
    int tot = 256 * cin * 9;
    if (idx < tot) {
        int k = idx % 9, rest = idx / 9;
        int ci = rest % cin, g = rest / cin;
        float v = w[idx];
        bf16 hi = __float2bfloat16(v);
        bf16 lo = __float2bfloat16(v - __bfloat162float(hi));
        size_t o = ((size_t)k * 256 + g) * cin + ci;
        dst[o] = hi;
        dst[(size_t)9 * 256 * cin + o] = lo;
    }
    if (bc && idx < 256) bc[idx] = ba[idx] + bb[idx];
}

// ---- features [b][t][128][px] fp32 -> g_ft[t*8+b][plane][px][128] bf16 --------
__global__ void feat_tr_k(const float* __restrict__ f)
{
    __shared__ float s[32][257];
    int img = blockIdx.x, cbk = blockIdx.y, pb = blockIdx.z, tid = threadIdx.x;
    int b = img & 7, t = img >> 3;
    const float* src = f + ((size_t)(b * TT + t) * 128 + cbk * 32) * PX + pb * 256;
#pragma unroll 8
    for (int r = 0; r < 32; r++) s[r][tid] = src[(size_t)r * PX + tid];
    __syncthreads();
    int ci = tid & 31, pl = tid >> 5;
    bf16* dh = g_ft + (size_t)(img * 2) * PX * 128;
    bf16* dl = dh + (size_t)PX * 128;
#pragma unroll 8
    for (int wv = 0; wv < 32; wv++) {
        int p = pb * 256 + wv * 8 + pl;
        float v = s[ci][wv * 8 + pl];
        bf16 hi = __float2bfloat16(v);
        dh[(size_t)p * 128 + cbk * 32 + ci] = hi;
        dl[(size_t)p * 128 + cbk * 32 + ci] = __float2bfloat16(v - __bfloat162float(hi));
    }
}

// ---- conv3x3 implicit GEMM via mma.sync bf16 ----------------------------------
template <int CIN, int MODE>
__global__ void __launch_bounds__(256)
conv_hmma(const bf16* __restrict__ act, const bf16* __restrict__ wpa,
          const bf16* __restrict__ wpb, const float* __restrict__ biasa,
          const float* __restrict__ biasb, float* __restrict__ gB)
{
    __shared__ bf16 sA[2][4096], sB[2][4096];
    const int tid = threadIdx.x, lane = tid & 31, wid = tid >> 5;
    const int wM = wid & 3, wN = wid >> 2;
    const int tile = blockIdx.x, ghalf = blockIdx.y, z = blockIdx.z;

    const bf16* wp = wpa;
    const float* bias = biasa;
    int slot = z;
    if (MODE == 0) { int dir = z >> 6; slot = z & 63; if (dir) { wp = wpb; bias = biasb; } }
    else if (MODE == 1) { int dir = z >> 3; if (dir) wp = wpb; }

    const size_t actps = (size_t)PX * CIN;
    const bf16* aimg = act + (size_t)slot * 2 * actps;
    float* gout = gB + (size_t)z * PX * 256;
    const size_t wps = (size_t)9 * 256 * CIN;
    const uint32_t sAu = smem_u32(sA), sBu = smem_u32(sB);

    float acc[2][8][4];
#pragma unroll
    for (int a = 0; a < 2; a++)
#pragma unroll
        for (int n = 0; n < 8; n++)
#pragma unroll
            for (int c = 0; c < 4; c++) acc[a][n][c] = 0.f;

    const int NH = CIN / 32, NIT = 27 * NH;
    const int arow = tid >> 1, ach = (tid & 1) * 2;
    const int gpxA = tile * 128 + arow;
    const int growB = ghalf * 128 + arow;

    auto issue = [&](int it) {
        int buf = it & 1;
        int term = it / (9 * NH), rem = it - term * (9 * NH);
        int k = rem / NH, half = rem - k * NH;
        int pa = (term == 1), pbw = (term == 2);
        int ys = (gpxA >> 5) + k / 3 - 1, xsv = (gpxA & 31) + k % 3 - 1;
        bool v = ((unsigned)ys < 32u) && ((unsigned)xsv < 32u);
        const char* asrc = (const char*)(aimg + (size_t)pa * actps +
                           (v ? (size_t)(ys * 32 + xsv) * CIN : (size_t)0) + half * 32);
        const char* bsrc = (const char*)(wp + (size_t)pbw * wps +
                           ((size_t)k * 256 + growB) * CIN + half * 32);
        uint32_t sz = v ? 16u : 0u;
#pragma unroll
        for (int i = 0; i < 2; i++) {
            int j = ach + i;
            uint32_t off = arow * 64 + j * 16;
            uint32_t swz = off ^ ((off >> 2) & 0x30);
            cp16(sAu + buf * 8192 + swz, asrc + j * 16, sz);
            cp16f(sBu + buf * 8192 + swz, bsrc + j * 16);
        }
        cp_commit();
    };

    const int aro = (lane & 7) + 8 * ((lane >> 3) & 1), acs = (lane >> 4) & 1;
    const int bro = (lane & 7) + 8 * ((lane >> 4) & 1), bcs = (lane >> 3) & 1;

    issue(0);
    for (int it = 0; it < NIT; it++) {
        if (it + 1 < NIT) { issue(it + 1); cp_wait1(); }
        else cp_wait0();
        __syncthreads();
        uint32_t sa = sAu + (it & 1) * 8192, sb = sBu + (it & 1) * 8192;
#pragma unroll
        for (int s = 0; s < 2; s++) {
            uint32_t af[2][4];
#pragma unroll
            for (int mi = 0; mi < 2; mi++) {
                uint32_t off = (uint32_t)(wM * 32 + mi * 16 + aro) * 64 + s * 32 + acs * 16;
                ldsm4(af[mi], sa + (off ^ ((off >> 2) & 0x30)));
            }
#pragma unroll
            for (int np = 0; np < 4; np++) {
                uint32_t bfr[4];
                uint32_t off = (uint32_t)(wN * 64 + np * 16 + bro) * 64 + s * 32 + bcs * 16;
                ldsm4(bfr, sb + (off ^ ((off >> 2) & 0x30)));   // non-trans: smem is [n][k]
#pragma unroll
                for (int mi = 0; mi < 2; mi++) {
                    mma16816(acc[mi][np * 2],     af[mi], bfr);
                    mma16816(acc[mi][np * 2 + 1], af[mi], bfr + 2);
                }
            }
        }
        __syncthreads();
    }

    const int r0 = wM * 32 + (lane >> 2), c0 = wN * 64 + (lane & 3) * 2;
#pragma unroll
    for (int mi = 0; mi < 2; mi++)
#pragma unroll
        for (int ni = 0; ni < 8; ni++) {
            int col = ghalf * 128 + c0 + ni * 8;
            float b0 = 0.f, b1 = 0.f;
            if (MODE != 1) { b0 = bias[col]; b1 = bias[col + 1]; }
            float* p0 = gout + (size_t)(tile * 128 + r0 + mi * 16) * 256 + col;
            float2 v0 = { acc[mi][ni][0] + b0, acc[mi][ni][1] + b1 };
            float2 v1 = { acc[mi][ni][2] + b0, acc[mi][ni][3] + b1 };
            *(float2*)p0 = v0;
            *(float2*)(p0 + 8 * 256) = v1;
        }
}

// ---- pointwise LSTM cell (pixel-major) ----------------------------------------
__global__ void cell_k(const float* __restrict__ gih, const float* __restrict__ ghh,
                       float* __restrict__ cB, bf16* __restrict__ hB,
                       bf16* __restrict__ xsB, float* __restrict__ lastB,
                       int t, int l1, int lco, int n)
{
    int i = blockIdx.x * 256 + threadIdx.x;
    if (i >= n) return;
    int ch = i & 63, px = (i >> 6) & 1023, im = i >> 16;
    int dir = im >> 3, b = im & 7;
    int teff = dir ? 7 - t : t;
    size_t gidx = l1 ? (((size_t)(t * 8 + b)) * PX + px) * 256
                     : (((size_t)(dir * 64 + teff * 8 + b)) * PX + px) * 256;
    float i_ = gih[gidx + ch], f_ = gih[gidx + 64 + ch];
    float g_ = gih[gidx + 128 + ch], o_ = gih[gidx + 192 + ch];
    float cp = 0.f;
    if (ghh) {
        size_t hx = ((size_t)im * PX + px) * 256;
        i_ += ghh[hx + ch]; f_ += ghh[hx + 64 + ch];
        g_ += ghh[hx + 128 + ch]; o_ += ghh[hx + 192 + ch];
        cp = cB[i];
    }
    float cn = sigf(f_) * cp + sigf(i_) * tanhf(g_);
    float hn = sigf(o_) * tanhf(cn);
    cB[i] = cn;
    bf16 hh_ = __float2bfloat16(hn);
    bf16 hl_ = __float2bfloat16(hn - __bfloat162float(hh_));
    size_t hb_ = ((size_t)im * 2 * PX + px) * 64 + ch;
    hB[hb_] = hh_;
    hB[hb_ + (size_t)PX * 64] = hl_;
    if (xsB) {
        size_t xb = (((size_t)(teff * 8 + b)) * 2 * PX + px) * 128 + dir * 64 + ch;
        xsB[xb] = hh_;
        xsB[xb + (size_t)PX * 128] = hl_;
    }
    if (lastB) lastB[((size_t)b * PX + px) * 128 + lco + ch] = hn;
}

// ---- 1x1 conv + ReLU head -------------------------------------------------------
__global__ void __launch_bounds__(256) head_k(const float* __restrict__ last,
                                              const float* __restrict__ w,
                                              const float* __restrict__ bias,
                                              float* __restrict__ out)
{
    __shared__ float sw[8192];
    __shared__ float sb[64];
    int b = blockIdx.x, pb = blockIdx.y, tid = threadIdx.x;
    for (int i = tid; i < 8192; i += 256) sw[i] = w[i];
    if (tid < 64) sb[tid] = bias[tid];
    __syncthreads();
    int px = pb * 256 + tid;
    const float4* lrow = (const float4*)(last + ((size_t)b * PX + px) * 128);
    float4 lv[32];
#pragma unroll
    for (int j = 0; j < 32; j++) lv[j] = lrow[j];
#pragma unroll 1
    for (int o = 0; o < 64; o++) {
        const float4* wr = (const float4*)(sw + o * 128);
        float acc = sb[o];
#pragma unroll
        for (int j = 0; j < 32; j++) {
            float4 wv = wr[j];
            acc += lv[j].x * wv.x + lv[j].y * wv.y + lv[j].z * wv.z + lv[j].w * wv.w;
        }
        out[((size_t)b * 64 + o) * PX + px] = fmaxf(acc, 0.f);
    }
}

// ---- host ------------------------------------------------------------------------
extern "C" void kernel_launch(void* const* d_in, const int* in_sizes, int n_in,
                              void* d_out, int out_size)
{
    const float* features = (const float*)d_in[0];
    const float* W[8]  = { (const float*)d_in[1],  (const float*)d_in[5],
                           (const float*)d_in[9],  (const float*)d_in[13],
                           (const float*)d_in[2],  (const float*)d_in[6],
                           (const float*)d_in[10], (const float*)d_in[14] };
    const float* BI[4] = { (const float*)d_in[3],  (const float*)d_in[7],
                           (const float*)d_in[11], (const float*)d_in[15] };
    const float* BH[4] = { (const float*)d_in[4],  (const float*)d_in[8],
                           (const float*)d_in[12], (const float*)d_in[16] };
    const float* w_out = (const float*)d_in[17];
    const float* b_out = (const float*)d_in[18];
    float* out = (float*)d_out;

    bf16 *ft, *xs1, *hb, *wpk;
    float *cb, *g0, *g1, *ghh, *last, *bc;
    cudaGetSymbolAddress((void**)&ft, g_ft);
    cudaGetSymbolAddress((void**)&xs1, g_xs1);
    cudaGetSymbolAddress((void**)&hb, g_hb);
    cudaGetSymbolAddress((void**)&cb, g_cb);
    cudaGetSymbolAddress((void**)&g0, g_g0);
    cudaGetSymbolAddress((void**)&g1, g_g1);
    cudaGetSymbolAddress((void**)&ghh, g_ghh);
    cudaGetSymbolAddress((void**)&last, g_lastb);
    cudaGetSymbolAddress((void**)&wpk, g_wpk);
    cudaGetSymbolAddress((void**)&bc, g_bc);

    bf16* wih[4]; bf16* whh[3];
    for (int s = 0; s < 4; s++) wih[s] = wpk + (size_t)s * 589824;
    for (int s = 0; s < 3; s++) whh[s] = wpk + (size_t)4 * 589824 + (size_t)s * 294912;

    for (int s = 0; s < 4; s++)
        repack_k<<<1152, 256>>>(W[s], BI[s], BH[s], wih[s], bc + s * 256, 128);
    for (int s = 0; s < 3; s++)
        repack_k<<<576, 256>>>(W[4 + s], nullptr, nullptr, whh[s], nullptr, 64);
    feat_tr_k<<<dim3(64, 4, 4), 256>>>(features);

    const size_t IMGZ = (size_t)PX * 256;
    const size_t CS = (size_t)PX * 64;
    const size_t HS = (size_t)2 * PX * 64;
    const int N16 = 16 * PX * 64, N8 = 8 * PX * 64;

    // ===== layer 0 =====
    conv_hmma<128, 0><<<dim3(8, 2, 128), 256>>>(ft, wih[0], wih[1], bc, bc + 256, g0);
    cell_k<<<N16 / 256, 256>>>(g0, nullptr, cb, hb, xs1, nullptr, 0, 0, 0, N16);
    for (int t = 1; t < TT; t++) {
        conv_hmma<64, 1><<<dim3(8, 2, 16), 256>>>(hb, whh[0], whh[1], nullptr, nullptr, ghh);
        cell_k<<<N16 / 256, 256>>>(g0, ghh, cb, hb, xs1, nullptr, t, 0, 0, N16);
    }

    // ===== layer 1 ih: forward all t; reverse only t=7 (hr1[-1]) =====
    conv_hmma<128, 2><<<dim3(8, 2, 64), 256>>>(xs1, wih[2], nullptr, bc + 512, nullptr, g1);
    conv_hmma<128, 2><<<dim3(8, 2, 8), 256>>>(xs1 + (size_t)56 * 2 * PX * 128,
                                              wih[3], nullptr, bc + 768, nullptr, g1 + 64 * IMGZ);

    // layer-1 reverse single cell step (h0=c0=0)
    cell_k<<<N8 / 256, 256>>>(g1 + 64 * IMGZ, nullptr, cb + 16 * CS, hb + 16 * HS,
                              nullptr, last, 0, 1, 64, N8);
    // layer-1 forward recurrence
    cell_k<<<N8 / 256, 256>>>(g1, nullptr, cb + 24 * CS, hb + 24 * HS,
                              nullptr, nullptr, 0, 1, 0, N8);
    for (int t = 1; t < TT; t++) {
        conv_hmma<64, 1><<<dim3(8, 2, 8), 256>>>(hb + 24 * HS, whh[2], whh[2],
                                                 nullptr, nullptr, ghh);
        cell_k<<<N8 / 256, 256>>>(g1, ghh, cb + 24 * CS, hb + 24 * HS,
                                  nullptr, (t == TT - 1) ? last : nullptr, t, 1, 0, N8);
    }

    head_k<<<dim3(8, 4), 256>>>(last, w_out, b_out, out);
}

// round 8
// speedup vs baseline: 3.6708x; 1.3114x over previous
#include <cuda_runtime.h>
#include <cuda_bf16.h>
#include <cstdint>

#define TT 8
#define PX 1024
typedef __nv_bfloat16 bf16;

// ---- scratch globals ----------------------------------------------------------
__device__ __align__(16) bf16  g_ft[(size_t)64 * 2 * PX * 128];
__device__ __align__(16) bf16  g_xs1[(size_t)64 * 2 * PX * 128];
__device__ __align__(16) bf16  g_hb[(size_t)32 * 2 * PX * 64];
__device__ __align__(16) float g_cb[(size_t)32 * PX * 64];
__device__ __align__(16) float g_g0[(size_t)128 * PX * 256];
__device__ __align__(16) float g_g1[(size_t)72 * PX * 256];
__device__ __align__(16) float g_lastb[(size_t)8 * PX * 128];
__device__ __align__(16) bf16  g_wpk[(size_t)4 * 589824 + (size_t)3 * 294912];
__device__ __align__(16) float g_bc[4 * 256];

// ---- helpers --------------------------------------------------------------------
__device__ __forceinline__ uint32_t smem_u32(const void* p) {
    uint32_t a;
    asm("{ .reg .u64 t; cvta.to.shared.u64 t, %1; cvt.u32.u64 %0, t; }" : "=r"(a) : "l"(p));
    return a;
}
__device__ __forceinline__ void ldsm4(uint32_t* r, uint32_t a) {
    asm volatile("ldmatrix.sync.aligned.m8n8.x4.shared.b16 {%0,%1,%2,%3}, [%4];"
        : "=r"(r[0]), "=r"(r[1]), "=r"(r[2]), "=r"(r[3]) : "r"(a));
}
__device__ __forceinline__ void mma16816(float* d, const uint32_t* a, const uint32_t* b) {
    asm volatile("mma.sync.aligned.m16n8k16.row.col.f32.bf16.bf16.f32 "
        "{%0,%1,%2,%3},{%4,%5,%6,%7},{%8,%9},{%0,%1,%2,%3};"
        : "+f"(d[0]), "+f"(d[1]), "+f"(d[2]), "+f"(d[3])
        : "r"(a[0]), "r"(a[1]), "r"(a[2]), "r"(a[3]), "r"(b[0]), "r"(b[1]));
}
__device__ __forceinline__ void cp16(uint32_t d, const void* s, uint32_t sz) {
    asm volatile("cp.async.ca.shared.global [%0], [%1], 16, %2;" :: "r"(d), "l"(s), "r"(sz) : "memory");
}
__device__ __forceinline__ void cp16f(uint32_t d, const void* s) {
    asm volatile("cp.async.ca.shared.global [%0], [%1], 16;" :: "r"(d), "l"(s) : "memory");
}
__device__ __forceinline__ void cp_commit() { asm volatile("cp.async.commit_group;" ::: "memory"); }
__device__ __forceinline__ void cp_wait0() { asm volatile("cp.async.wait_group 0;" ::: "memory"); }
__device__ __forceinline__ void cp_wait1() { asm volatile("cp.async.wait_group 1;" ::: "memory"); }
__device__ __forceinline__ float sigf(float x) { return 1.f / (1.f + __expf(-x)); }

// ---- weight repack -> bf16 hi|lo planes, PERMUTED gate rows g'=(g%64)*4+g/64 ----
__global__ void repack_k(const float* __restrict__ w, const float* __restrict__ ba,
                         const float* __restrict__ bb, bf16* __restrict__ dst,
                         float* __restrict__ bc, int cin)
{
    int idx = blockIdx.x * 256 + threadIdx.x;
    int tot = 256 * cin * 9;
    if (idx < tot) {
        int k = idx % 9, rest = idx / 9;
        int ci = rest % cin, g = rest / cin;
        int gp = (g & 63) * 4 + (g >> 6);
        float v = w[idx];
        bf16 hi = __float2bfloat16(v);
        bf16 lo = __float2bfloat16(v - __bfloat162float(hi));
        size_t o = ((size_t)k * 256 + gp) * cin + ci;
        dst[o] = hi;
        dst[(size_t)9 * 256 * cin + o] = lo;
    }
    if (bc && idx < 256)
        bc[(idx & 63) * 4 + (idx >> 6)] = ba[idx] + bb[idx];
}

// ---- features fp32 [b][t][128][px] -> g_ft[t*8+b][plane][px][128] bf16 ----------
__global__ void feat_tr_k(const float* __restrict__ f)
{
    __shared__ float s[32][257];
    int img = blockIdx.x, cbk = blockIdx.y, pb = blockIdx.z, tid = threadIdx.x;
    int b = img & 7, t = img >> 3;
    const float* src = f + ((size_t)(b * TT + t) * 128 + cbk * 32) * PX + pb * 256;
#pragma unroll 8
    for (int r = 0; r < 32; r++) s[r][tid] = src[(size_t)r * PX + tid];
    __syncthreads();
    int ci = tid & 31, pl = tid >> 5;
    bf16* dh = g_ft + (size_t)(img * 2) * PX * 128;
    bf16* dl = dh + (size_t)PX * 128;
#pragma unroll 8
    for (int wv = 0; wv < 32; wv++) {
        int p = pb * 256 + wv * 8 + pl;
        float v = s[ci][wv * 8 + pl];
        bf16 hi = __float2bfloat16(v);
        dh[(size_t)p * 128 + cbk * 32 + ci] = hi;
        dl[(size_t)p * 128 + cbk * 32 + ci] = __float2bfloat16(v - __bfloat162float(hi));
    }
}

// ---- conv3x3 implicit GEMM, K=64 stages, staged epilogue ------------------------
// MODE0: L0 ih (z=dir*64+t*8+b) -> gates.  MODE2: L1 ih (z=slot) -> gates.
// MODE1: L0 hh fused cell (z=dir*8+b).     MODE3: L1f hh fused cell (z=b).
template <int CIN, int MODE>
__global__ void __launch_bounds__(256)
conv_hmma(const bf16* __restrict__ act, const bf16* __restrict__ wpa,
          const bf16* __restrict__ wpb, const float* __restrict__ biasa,
          const float* __restrict__ biasb, float* __restrict__ gB,
          float* __restrict__ cB, bf16* __restrict__ hB,
          bf16* __restrict__ xsB, float* __restrict__ lastB, int t)
{
    extern __shared__ __align__(16) char sm[];
    const int tid = threadIdx.x, lane = tid & 31, wid = tid >> 5;
    const int wM = wid & 3, wN = wid >> 2;
    const int tile = blockIdx.x, ghalf = blockIdx.y, z = blockIdx.z;

    const bf16* wp = wpa;
    const float* bias = biasa;
    int slot = z, aimg = 0, xslot = 0, choff = 0;
    if (MODE == 0) { int dir = z >> 6; slot = z & 63; if (dir) { wp = wpb; bias = biasb; } }
    else if (MODE == 1) {
        int dir = z >> 3, b_ = z & 7;
        if (dir) wp = wpb;
        int teff = dir ? 7 - t : t;
        aimg = dir * 64 + teff * 8 + b_;
        xslot = teff * 8 + b_; choff = dir * 64;
    } else if (MODE == 3) { aimg = t * 8 + z; }

    const size_t actps = (size_t)PX * CIN;
    const bf16* aimg_p = act + (size_t)slot * 2 * actps;
    const size_t wps = (size_t)9 * 256 * CIN;
    const uint32_t su = smem_u32(sm);

    float acc[2][8][4];
#pragma unroll
    for (int a = 0; a < 2; a++)
#pragma unroll
        for (int n = 0; n < 8; n++)
#pragma unroll
            for (int c = 0; c < 4; c++) acc[a][n][c] = 0.f;

    const int NH = CIN / 64, NIT = 27 * NH;
    const int lrow = tid >> 1, seg = (tid & 1) * 64;
    const int gpxA = tile * 128 + lrow;

    auto issue = [&](int it) {
        int buf = it & 1;
        int term = it / (9 * NH), rem = it - term * (9 * NH);
        int k = rem / NH, half = rem - k * NH;
        int pa = (term == 1), pbw = (term == 2);
        int ys = (gpxA >> 5) + k / 3 - 1, xsv = (gpxA & 31) + k % 3 - 1;
        bool v = ((unsigned)ys < 32u) && ((unsigned)xsv < 32u);
        const char* asrc = (const char*)(aimg_p + (size_t)pa * actps +
                           (v ? (size_t)(ys * 32 + xsv) * CIN : (size_t)0) + half * 64) + seg;
        const char* bsrc = (const char*)(wp + (size_t)pbw * wps +
                           ((size_t)k * 256 + ghalf * 128 + lrow) * CIN + half * 64) + seg;
        uint32_t ab = su + buf * 32768 + lrow * 128;
        uint32_t bb_ = ab + 16384;
        uint32_t sz = v ? 16u : 0u;
#pragma unroll
        for (int j = 0; j < 4; j++) {
            uint32_t off = seg + j * 16;
            uint32_t swz = off ^ ((lrow & 7) << 4);
            cp16(ab + swz, asrc + j * 16, sz);
            cp16f(bb_ + swz, bsrc + j * 16);
        }
        cp_commit();
    };

    const int aro = (lane & 7) + 8 * ((lane >> 3) & 1), acs = (lane >> 4) & 1;
    const int bro = (lane & 7) + 8 * ((lane >> 4) & 1), bcs = (lane >> 3) & 1;

    issue(0);
    for (int it = 0; it < NIT; it++) {
        if (it + 1 < NIT) { issue(it + 1); cp_wait1(); }
        else cp_wait0();
        __syncthreads();
        uint32_t sa = su + (it & 1) * 32768, sb = sa + 16384;
#pragma unroll
        for (int s = 0; s < 4; s++) {
            uint32_t af[2][4];
#pragma unroll
            for (int mi = 0; mi < 2; mi++) {
                int row = wM * 32 + mi * 16 + aro;
                ldsm4(af[mi], sa + row * 128 + ((2 * s + acs) ^ (row & 7)) * 16);
            }
#pragma unroll
            for (int np = 0; np < 4; np++) {
                uint32_t bfr[4];
                int row = wN * 64 + np * 16 + bro;
                ldsm4(bfr, sb + row * 128 + ((2 * s + bcs) ^ (row & 7)) * 16);
#pragma unroll
                for (int mi = 0; mi < 2; mi++) {
                    mma16816(acc[mi][np * 2],     af[mi], bfr);
                    mma16816(acc[mi][np * 2 + 1], af[mi], bfr + 2);
                }
            }
        }
        __syncthreads();
    }

    // ---- stage accs to smem (stride 130 floats) ----
    float* st = (float*)sm;
    const int r0 = wM * 32 + (lane >> 2), c0 = wN * 64 + (lane & 3) * 2;
#pragma unroll
    for (int mi = 0; mi < 2; mi++)
#pragma unroll
        for (int ni = 0; ni < 8; ni++) {
            int r = r0 + mi * 16, c = c0 + ni * 8;
            *(float2*)(st + r * 130 + c)       = *(float2*)acc[mi][ni];
            *(float2*)(st + (r + 8) * 130 + c) = *(float2*)(acc[mi][ni] + 2);
        }
    __syncthreads();

    if (MODE == 0 || MODE == 2) {
        float* gout = gB + (size_t)z * PX * 256;
        float4 bq = *(const float4*)(bias + ghalf * 128 + lane * 4);
#pragma unroll 1
        for (int it = 0; it < 16; it++) {
            int px = wid + 8 * it;
            float2 a01 = *(float2*)(st + px * 130 + lane * 4);
            float2 a23 = *(float2*)(st + px * 130 + lane * 4 + 2);
            float4 o = { a01.x + bq.x, a01.y + bq.y, a23.x + bq.z, a23.y + bq.w };
            *(float4*)(gout + (size_t)(tile * 128 + px) * 256 + ghalf * 128 + lane * 4) = o;
        }
    } else {
        const int gch = ghalf * 32 + lane;
#pragma unroll 1
        for (int it = 0; it < 16; it++) {
            int px = wid + 8 * it;
            int gpx = tile * 128 + px;
            float2 a01 = *(float2*)(st + px * 130 + lane * 4);
            float2 a23 = *(float2*)(st + px * 130 + lane * 4 + 2);
            float4 g4 = *(const float4*)(gB + ((size_t)aimg * PX + gpx) * 256 + gch * 4);
            float i_ = a01.x + g4.x, f_ = a01.y + g4.y;
            float g_ = a23.x + g4.z, o_ = a23.y + g4.w;
            size_t ci = ((size_t)z * PX + gpx) * 64 + gch;
            float cp = cB[ci];
            float cn = sigf(f_) * cp + sigf(i_) * tanhf(g_);
            float hn = sigf(o_) * tanhf(cn);
            cB[ci] = cn;
            bf16 hh_ = __float2bfloat16(hn);
            bf16 hl_ = __float2bfloat16(hn - __bfloat162float(hh_));
            size_t hi_ = ((size_t)z * 2 * PX + gpx) * 64 + gch;
            hB[hi_] = hh_;
            hB[hi_ + (size_t)PX * 64] = hl_;
            if (MODE == 1) {
                size_t xb = ((size_t)(xslot * 2) * PX + gpx) * 128 + choff + gch;
                xsB[xb] = hh_;
                xsB[xb + (size_t)PX * 128] = hl_;
            }
            if (MODE == 3 && lastB)
                lastB[((size_t)z * PX + gpx) * 128 + gch] = hn;
        }
    }
}

// ---- standalone cell for zero-init steps (reads permuted gate quads) ------------
__global__ void cell_k(const float* __restrict__ gih, float* __restrict__ cB,
                       bf16* __restrict__ hB, bf16* __restrict__ xsB,
                       float* __restrict__ lastB, int mode, int lco, int n)
{
    int i = blockIdx.x * 256 + threadIdx.x;
    if (i >= n) return;
    int ch = i & 63, px = (i >> 6) & 1023, im = i >> 16;
    int gslot = im, xslot = 0, choff = 0;
    if (mode == 0) {
        int dir = im >> 3, b = im & 7;
        int teff = dir ? 7 : 0;
        gslot = dir * 64 + teff * 8 + b;
        xslot = teff * 8 + b; choff = dir * 64;
    }
    float4 g4 = *(const float4*)(gih + ((size_t)gslot * PX + px) * 256 + ch * 4);
    float cn = sigf(g4.x) * tanhf(g4.z);
    float hn = sigf(g4.w) * tanhf(cn);
    cB[i] = cn;
    bf16 hh_ = __float2bfloat16(hn);
    bf16 hl_ = __float2bfloat16(hn - __bfloat162float(hh_));
    size_t hb_ = ((size_t)im * 2 * PX + px) * 64 + ch;
    hB[hb_] = hh_;
    hB[hb_ + (size_t)PX * 64] = hl_;
    if (xsB) {
        size_t xb = ((size_t)(xslot * 2) * PX + px) * 128 + choff + ch;
        xsB[xb] = hh_;
        xsB[xb + (size_t)PX * 128] = hl_;
    }
    if (lastB) lastB[((size_t)im * PX + px) * 128 + lco + ch] = hn;
}

// ---- 1x1 conv + ReLU head ---------------------------------------------------------
__global__ void __launch_bounds__(256) head_k(const float* __restrict__ last,
                                              const float* __restrict__ w,
                                              const float* __restrict__ bias,
                                              float* __restrict__ out)
{
    __shared__ float sw[8192];
    __shared__ float sb[64];
    int b = blockIdx.x, pb = blockIdx.y, tid = threadIdx.x;
    for (int i = tid; i < 8192; i += 256) sw[i] = w[i];
    if (tid < 64) sb[tid] = bias[tid];
    __syncthreads();
    int px = pb * 256 + tid;
    const float4* lrow = (const float4*)(last + ((size_t)b * PX + px) * 128);
    float4 lv[32];
#pragma unroll
    for (int j = 0; j < 32; j++) lv[j] = lrow[j];
#pragma unroll 1
    for (int o = 0; o < 64; o++) {
        const float4* wr = (const float4*)(sw + o * 128);
        float acc = sb[o];
#pragma unroll
        for (int j = 0; j < 32; j++) {
            float4 wv = wr[j];
            acc += lv[j].x * wv.x + lv[j].y * wv.y + lv[j].z * wv.z + lv[j].w * wv.w;
        }
        out[((size_t)b * 64 + o) * PX + px] = fmaxf(acc, 0.f);
    }
}

// ---- host ---------------------------------------------------------------------------
extern "C" void kernel_launch(void* const* d_in, const int* in_sizes, int n_in,
                              void* d_out, int out_size)
{
    const float* features = (const float*)d_in[0];
    const float* W[8]  = { (const float*)d_in[1],  (const float*)d_in[5],
                           (const float*)d_in[9],  (const float*)d_in[13],
                           (const float*)d_in[2],  (const float*)d_in[6],
                           (const float*)d_in[10], (const float*)d_in[14] };
    const float* BI[4] = { (const float*)d_in[3],  (const float*)d_in[7],
                           (const float*)d_in[11], (const float*)d_in[15] };
    const float* BH[4] = { (const float*)d_in[4],  (const float*)d_in[8],
                           (const float*)d_in[12], (const float*)d_in[16] };
    const float* w_out = (const float*)d_in[17];
    const float* b_out = (const float*)d_in[18];
    float* out = (float*)d_out;

    bf16 *ft, *xs1, *hb, *wpk;
    float *cb, *g0, *g1, *last, *bc;
    cudaGetSymbolAddress((void**)&ft, g_ft);
    cudaGetSymbolAddress((void**)&xs1, g_xs1);
    cudaGetSymbolAddress((void**)&hb, g_hb);
    cudaGetSymbolAddress((void**)&cb, g_cb);
    cudaGetSymbolAddress((void**)&g0, g_g0);
    cudaGetSymbolAddress((void**)&g1, g_g1);
    cudaGetSymbolAddress((void**)&last, g_lastb);
    cudaGetSymbolAddress((void**)&wpk, g_wpk);
    cudaGetSymbolAddress((void**)&bc, g_bc);

    bf16* wih[4]; bf16* whh[3];
    for (int s = 0; s < 4; s++) wih[s] = wpk + (size_t)s * 589824;
    for (int s = 0; s < 3; s++) whh[s] = wpk + (size_t)4 * 589824 + (size_t)s * 294912;

    const int DSMEM = 128 * 130 * 4;   // 66560 >= pipeline 65536
    cudaFuncSetAttribute(conv_hmma<128, 0>, cudaFuncAttributeMaxDynamicSharedMemorySize, DSMEM);
    cudaFuncSetAttribute(conv_hmma<128, 2>, cudaFuncAttributeMaxDynamicSharedMemorySize, DSMEM);
    cudaFuncSetAttribute(conv_hmma<64, 1>,  cudaFuncAttributeMaxDynamicSharedMemorySize, DSMEM);
    cudaFuncSetAttribute(conv_hmma<64, 3>,  cudaFuncAttributeMaxDynamicSharedMemorySize, DSMEM);

    for (int s = 0; s < 4; s++)
        repack_k<<<1152, 256>>>(W[s], BI[s], BH[s], wih[s], bc + s * 256, 128);
    for (int s = 0; s < 3; s++)
        repack_k<<<576, 256>>>(W[4 + s], nullptr, nullptr, whh[s], nullptr, 64);
    feat_tr_k<<<dim3(64, 4, 4), 256>>>(features);

    const size_t IMGZ = (size_t)PX * 256;
    const size_t CS = (size_t)PX * 64;
    const size_t HS = (size_t)2 * PX * 64;
    const int N16 = 16 * PX * 64, N8 = 8 * PX * 64;

    // ===== layer 0 =====
    conv_hmma<128, 0><<<dim3(8, 2, 128), 256, DSMEM>>>(
        ft, wih[0], wih[1], bc, bc + 256, g0, nullptr, nullptr, nullptr, nullptr, 0);
    cell_k<<<N16 / 256, 256>>>(g0, cb, hb, xs1, nullptr, 0, 0, N16);
    for (int t = 1; t < TT; t++)
        conv_hmma<64, 1><<<dim3(8, 2, 16), 256, DSMEM>>>(
            hb, whh[0], whh[1], nullptr, nullptr, g0, cb, hb, xs1, nullptr, t);

    // ===== layer 1 ih: forward all t; reverse only t=7 =====
    conv_hmma<128, 2><<<dim3(8, 2, 64), 256, DSMEM>>>(
        xs1, wih[2], nullptr, bc + 512, nullptr, g1, nullptr, nullptr, nullptr, nullptr, 0);
    conv_hmma<128, 2><<<dim3(8, 2, 8), 256, DSMEM>>>(
        xs1 + (size_t)56 * 2 * PX * 128, wih[3], nullptr, bc + 768, nullptr,
        g1 + 64 * IMGZ, nullptr, nullptr, nullptr, nullptr, 0);

    // layer-1 reverse single step (h0=c0=0) -> last[:,64:]
    cell_k<<<N8 / 256, 256>>>(g1 + 64 * IMGZ, cb + 16 * CS, hb + 16 * HS,
                              nullptr, last, 1, 64, N8);
    // layer-1 forward recurrence
    cell_k<<<N8 / 256, 256>>>(g1, cb + 24 * CS, hb + 24 * HS, nullptr, nullptr, 1, 0, N8);
    for (int t = 1; t < TT; t++)
        conv_hmma<64, 3><<<dim3(8, 2, 8), 256, DSMEM>>>(
            hb + 24 * HS, whh[2], nullptr, nullptr, nullptr, g1,
            cb + 24 * CS, hb + 24 * HS, nullptr, (t == TT - 1) ? last : nullptr, t);

    head_k<<<dim3(8, 4), 256>>>(last, w_out, b_out, out);
}

// round 9
// speedup vs baseline: 3.7208x; 1.0136x over previous
#include <cuda_runtime.h>
#include <cuda_bf16.h>
#include <cstdint>

#define TT 8
#define PX 1024
typedef __nv_bfloat16 bf16;

__device__ __align__(16) bf16  g_ft[(size_t)64 * 2 * PX * 128];
__device__ __align__(16) bf16  g_xs1[(size_t)64 * 2 * PX * 128];
__device__ __align__(16) bf16  g_hb[(size_t)32 * 2 * PX * 64];
__device__ __align__(16) float g_cb[(size_t)32 * PX * 64];
__device__ __align__(16) float g_g0[(size_t)128 * PX * 256];
__device__ __align__(16) float g_g1[(size_t)72 * PX * 256];
__device__ __align__(16) float g_lastb[(size_t)8 * PX * 128];
__device__ __align__(16) bf16  g_wpk[(size_t)4 * 589824 + (size_t)3 * 294912];
__device__ __align__(16) float g_bc[4 * 256];
__device__ const float* g_wptr[8];
__device__ const float* g_biptr[4];
__device__ const float* g_bhptr[4];

__device__ __forceinline__ uint32_t smem_u32(const void* p) {
    uint32_t a;
    asm("{ .reg .u64 t; cvta.to.shared.u64 t, %1; cvt.u32.u64 %0, t; }" : "=r"(a) : "l"(p));
    return a;
}
__device__ __forceinline__ void ldsm4(uint32_t* r, uint32_t a) {
    asm volatile("ldmatrix.sync.aligned.m8n8.x4.shared.b16 {%0,%1,%2,%3}, [%4];"
        : "=r"(r[0]), "=r"(r[1]), "=r"(r[2]), "=r"(r[3]) : "r"(a));
}
__device__ __forceinline__ void mma16816(float* d, const uint32_t* a, const uint32_t* b) {
    asm volatile("mma.sync.aligned.m16n8k16.row.col.f32.bf16.bf16.f32 "
        "{%0,%1,%2,%3},{%4,%5,%6,%7},{%8,%9},{%0,%1,%2,%3};"
        : "+f"(d[0]), "+f"(d[1]), "+f"(d[2]), "+f"(d[3])
        : "r"(a[0]), "r"(a[1]), "r"(a[2]), "r"(a[3]), "r"(b[0]), "r"(b[1]));
}
__device__ __forceinline__ void cp16(uint32_t d, const void* s, uint32_t sz) {
    asm volatile("cp.async.ca.shared.global [%0], [%1], 16, %2;" :: "r"(d), "l"(s), "r"(sz) : "memory");
}
__device__ __forceinline__ void cp16f(uint32_t d, const void* s) {
    asm volatile("cp.async.ca.shared.global [%0], [%1], 16;" :: "r"(d), "l"(s) : "memory");
}
__device__ __forceinline__ void cp_commit() { asm volatile("cp.async.commit_group;" ::: "memory"); }
__device__ __forceinline__ void cp_wait0() { asm volatile("cp.async.wait_group 0;" ::: "memory"); }
__device__ __forceinline__ void cp_wait1() { asm volatile("cp.async.wait_group 1;" ::: "memory"); }
__device__ __forceinline__ float sigf(float x) { return 1.f / (1.f + __expf(-x)); }

__global__ void setptr_k(const float* w0, const float* w1, const float* w2, const float* w3,
                         const float* w4, const float* w5, const float* w6,
                         const float* bi0, const float* bi1, const float* bi2, const float* bi3,
                         const float* bh0, const float* bh1, const float* bh2, const float* bh3)
{
    g_wptr[0] = w0; g_wptr[1] = w1; g_wptr[2] = w2; g_wptr[3] = w3;
    g_wptr[4] = w4; g_wptr[5] = w5; g_wptr[6] = w6;
    g_biptr[0] = bi0; g_biptr[1] = bi1; g_biptr[2] = bi2; g_biptr[3] = bi3;
    g_bhptr[0] = bh0; g_bhptr[1] = bh1; g_bhptr[2] = bh2; g_bhptr[3] = bh3;
}

__global__ void repack_all(bf16* __restrict__ wdst, float* __restrict__ bc)
{
    int s = blockIdx.y;
    int cin = (s < 4) ? 128 : 64;
    int tot = 256 * cin * 9;
    int idx = blockIdx.x * 256 + threadIdx.x;
    bf16* dst = (s < 4) ? wdst + (size_t)s * 589824
                        : wdst + (size_t)4 * 589824 + (size_t)(s - 4) * 294912;
    if (idx < tot) {
        const float* w = g_wptr[s];
        int k = idx % 9, rest = idx / 9;
        int ci = rest % cin, g = rest / cin;
        int gp = (g & 63) * 4 + (g >> 6);
        float v = w[idx];
        bf16 hi = __float2bfloat16(v);
        bf16 lo = __float2bfloat16(v - __bfloat162float(hi));
        size_t o = ((size_t)k * 256 + gp) * cin + ci;
        dst[o] = hi;
        dst[(size_t)9 * 256 * cin + o] = lo;
    }
    if (s < 4 && blockIdx.x == 0 && threadIdx.x < 256) {
        int g = threadIdx.x;
        bc[s * 256 + (g & 63) * 4 + (g >> 6)] = g_biptr[s][g] + g_bhptr[s][g];
    }
}

__global__ void feat_tr_k(const float* __restrict__ f)
{
    __shared__ float s[32][257];
    int img = blockIdx.x, cbk = blockIdx.y, pb = blockIdx.z, tid = threadIdx.x;
    int b = img & 7, t = img >> 3;
    const float* src = f + ((size_t)(b * TT + t) * 128 + cbk * 32) * PX + pb * 256;
#pragma unroll 8
    for (int r = 0; r < 32; r++) s[r][tid] = src[(size_t)r * PX + tid];
    __syncthreads();
    int ci = tid & 31, pl = tid >> 5;
    bf16* dh = g_ft + (size_t)(img * 2) * PX * 128;
    bf16* dl = dh + (size_t)PX * 128;
#pragma unroll 8
    for (int wv = 0; wv < 32; wv++) {
        int p = pb * 256 + wv * 8 + pl;
        float v = s[ci][wv * 8 + pl];
        bf16 hi = __float2bfloat16(v);
        dh[(size_t)p * 128 + cbk * 32 + ci] = hi;
        dl[(size_t)p * 128 + cbk * 32 + ci] = __float2bfloat16(v - __bfloat162float(hi));
    }
}

template <int CIN, int MODE>
__global__ void __launch_bounds__(256, 2)
conv_hmma(const bf16* __restrict__ act, const bf16* __restrict__ wpa,
          const bf16* __restrict__ wpb, const float* __restrict__ biasa,
          const float* __restrict__ biasb, float* __restrict__ gB,
          float* __restrict__ cB, bf16* __restrict__ hB,
          bf16* __restrict__ xsB, float* __restrict__ lastB, int t)
{
    extern __shared__ __align__(16) char sm[];
    const int tid = threadIdx.x, lane = tid & 31, wid = tid >> 5;
    const int wM = wid & 3, wN = wid >> 2;
    const int tile = blockIdx.x, ghalf = blockIdx.y, z = blockIdx.z;

    const bf16* wp = wpa;
    const float* bias = biasa;
    int slot = z, aimg = 0, xslot = 0, choff = 0;
    if (MODE == 0) { int dir = z >> 6; slot = z & 63; if (dir) { wp = wpb; bias = biasb; } }
    else if (MODE == 1) {
        int dir = z >> 3, b_ = z & 7;
        if (dir) wp = wpb;
        int teff = dir ? 7 - t : t;
        aimg = dir * 64 + teff * 8 + b_;
        xslot = teff * 8 + b_; choff = dir * 64;
    } else if (MODE == 3) { aimg = t * 8 + z; }

    const size_t actps = (size_t)PX * CIN;
    const bf16* aimg_p = act + (size_t)slot * 2 * actps;
    const size_t wps = (size_t)9 * 256 * CIN;
    const uint32_t su = smem_u32(sm);

    float acc[2][8][4];
#pragma unroll
    for (int a = 0; a < 2; a++)
#pragma unroll
        for (int n = 0; n < 8; n++)
#pragma unroll
            for (int c = 0; c < 4; c++) acc[a][n][c] = 0.f;

    const int NH = CIN / 64, NIT = 27 * NH;
    const int lrow = tid >> 1, seg = (tid & 1) * 64;
    const int gpxA = tile * 128 + lrow;

    auto issue = [&](int it) {
        int buf = it % 3;
        int term = it / (9 * NH), rem = it - term * (9 * NH);
        int k = rem / NH, half = rem - k * NH;
        int pa = (term == 1), pbw = (term == 2);
        int ys = (gpxA >> 5) + k / 3 - 1, xsv = (gpxA & 31) + k % 3 - 1;
        bool v = ((unsigned)ys < 32u) && ((unsigned)xsv < 32u);
        const char* asrc = (const char*)(aimg_p + (size_t)pa * actps +
                           (v ? (size_t)(ys * 32 + xsv) * CIN : (size_t)0) + half * 64) + seg;
        const char* bsrc = (const char*)(wp + (size_t)pbw * wps +
                           ((size_t)k * 256 + ghalf * 128 + lrow) * CIN + half * 64) + seg;
        uint32_t ab = su + buf * 32768 + lrow * 128;
        uint32_t bb_ = ab + 16384;
        uint32_t sz = v ? 16u : 0u;
#pragma unroll
        for (int j = 0; j < 4; j++) {
            uint32_t off = seg + j * 16;
            uint32_t swz = off ^ ((lrow & 7) << 4);
            cp16(ab + swz, asrc + j * 16, sz);
            cp16f(bb_ + swz, bsrc + j * 16);
        }
        cp_commit();
    };

    const int aro = (lane & 7) + 8 * ((lane >> 3) & 1), acs = (lane >> 4) & 1;
    const int bro = (lane & 7) + 8 * ((lane >> 4) & 1), bcs = (lane >> 3) & 1;

    issue(0);
    issue(1);
    for (int it = 0; it < NIT; it++) {
        if (it < NIT - 1) cp_wait1(); else cp_wait0();
        __syncthreads();
        if (it + 2 < NIT) issue(it + 2);
        uint32_t sa = su + (it % 3) * 32768, sb = sa + 16384;
#pragma unroll
        for (int s = 0; s < 4; s++) {
            uint32_t af[2][4];
#pragma unroll
            for (int mi = 0; mi < 2; mi++) {
                int row = wM * 32 + mi * 16 + aro;
                ldsm4(af[mi], sa + row * 128 + ((2 * s + acs) ^ (row & 7)) * 16);
            }
#pragma unroll
            for (int np = 0; np < 4; np++) {
                uint32_t bfr[4];
                int row = wN * 64 + np * 16 + bro;
                ldsm4(bfr, sb + row * 128 + ((2 * s + bcs) ^ (row & 7)) * 16);
#pragma unroll
                for (int mi = 0; mi < 2; mi++) {
                    mma16816(acc[mi][np * 2],     af[mi], bfr);
                    mma16816(acc[mi][np * 2 + 1], af[mi], bfr + 2);
                }
            }
        }
    }
    __syncthreads();

    float* st = (float*)sm;
    const int r0 = wM * 32 + (lane >> 2), c0 = wN * 64 + (lane & 3) * 2;
#pragma unroll
    for (int mi = 0; mi < 2; mi++)
#pragma unroll
        for (int ni = 0; ni < 8; ni++) {
            int r = r0 + mi * 16, c = c0 + ni * 8;
            *(float2*)(st + r * 130 + c)       = *(float2*)acc[mi][ni];
            *(float2*)(st + (r + 8) * 130 + c) = *(float2*)(acc[mi][ni] + 2);
        }
    __syncthreads();

    if (MODE == 0 || MODE == 2) {
        float* gout = gB + (size_t)z * PX * 256;
        float4 bq = *(const float4*)(bias + ghalf * 128 + lane * 4);
#pragma unroll 1
        for (int it = 0; it < 16; it++) {
            int px = wid + 8 * it;
            float2 a01 = *(float2*)(st + px * 130 + lane * 4);
            float2 a23 = *(float2*)(st + px * 130 + lane * 4 + 2);
            float4 o = { a01.x + bq.x, a01.y + bq.y, a23.x + bq.z, a23.y + bq.w };
            *(float4*)(gout + (size_t)(tile * 128 + px) * 256 + ghalf * 128 + lane * 4) = o;
        }
    } else {
        const int gch = ghalf * 32 + lane;
#pragma unroll 1
        for (int it = 0; it < 16; it++) {
            int px = wid + 8 * it;
            int gpx = tile * 128 + px;
            float2 a01 = *(float2*)(st + px * 130 + lane * 4);
            float2 a23 = *(float2*)(st + px * 130 + lane * 4 + 2);
            float4 g4 = *(const float4*)(gB + ((size_t)aimg * PX + gpx) * 256 + gch * 4);
            float i_ = a01.x + g4.x, f_ = a01.y + g4.y;
            float g_ = a23.x + g4.z, o_ = a23.y + g4.w;
            size_t ci = ((size_t)z * PX + gpx) * 64 + gch;
            float cp = cB[ci];
            float cn = sigf(f_) * cp + sigf(i_) * tanhf(g_);
            float hn = sigf(o_) * tanhf(cn);
            cB[ci] = cn;
            bf16 hh_ = __float2bfloat16(hn);
            bf16 hl_ = __float2bfloat16(hn - __bfloat162float(hh_));
            size_t hi_ = ((size_t)z * 2 * PX + gpx) * 64 + gch;
            hB[hi_] = hh_;
            hB[hi_ + (size_t)PX * 64] = hl_;
            if (MODE == 1) {
                size_t xb = ((size_t)(xslot * 2) * PX + gpx) * 128 + choff + gch;
                xsB[xb] = hh_;
                xsB[xb + (size_t)PX * 128] = hl_;
            }
            if (MODE == 3 && lastB)
                lastB[((size_t)z * PX + gpx) * 128 + gch] = hn;
        }
    }
}

__global__ void cell_k(const float* __restrict__ gih, float* __restrict__ cB,
                       bf16* __restrict__ hB, bf16* __restrict__ xsB,
                       float* __restrict__ lastB, int mode, int lco, int n)
{
    int i = blockIdx.x * 256 + threadIdx.x;
    if (i >= n) return;
    int ch = i & 63, px = (i >> 6) & 1023, im = i >> 16;
    int gslot = im, xslot = 0, choff = 0;
    if (mode == 0) {
        int dir = im >> 3, b = im & 7;
        int teff = dir ? 7 : 0;
        gslot = dir * 64 + teff * 8 + b;
        xslot = teff * 8 + b; choff = dir * 64;
    }
    float4 g4 = *(const float4*)(gih + ((size_t)gslot * PX + px) * 256 + ch * 4);
    float cn = sigf(g4.x) * tanhf(g4.z);
    float hn = sigf(g4.w) * tanhf(cn);
    cB[i] = cn;
    bf16 hh_ = __float2bfloat16(hn);
    bf16 hl_ = __float2bfloat16(hn - __bfloat162float(hh_));
    size_t hb_ = ((size_t)im * 2 * PX + px) * 64 + ch;
    hB[hb_] = hh_;
    hB[hb_ + (size_t)PX * 64] = hl_;
    if (xsB) {
        size_t xb = ((size_t)(xslot * 2) * PX + px) * 128 + choff + ch;
        xsB[xb] = hh_;
        xsB[xb + (size_t)PX * 128] = hl_;
    }
    if (lastB) lastB[((size_t)im * PX + px) * 128 + lco + ch] = hn;
}

__global__ void __launch_bounds__(256) head_k(const float* __restrict__ last,
                                              const float* __restrict__ w,
                                              const float* __restrict__ bias,
                                              float* __restrict__ out)
{
    __shared__ float sw[8192];
    __shared__ float sb[64];
    int b = blockIdx.x, pb = blockIdx.y, tid = threadIdx.x;
    for (int i = tid; i < 8192; i += 256) sw[i] = w[i];
    if (tid < 64) sb[tid] = bias[tid];
    __syncthreads();
    int px = pb * 256 + tid;
    const float4* lrow = (const float4*)(last + ((size_t)b * PX + px) * 128);
    float4 lv[32];
#pragma unroll
    for (int j = 0; j < 32; j++) lv[j] = lrow[j];
#pragma unroll 1
    for (int o = 0; o < 64; o++) {
        const float4* wr = (const float4*)(sw + o * 128);
        float acc = sb[o];
#pragma unroll
        for (int j = 0; j < 32; j++) {
            float4 wv = wr[j];
            acc += lv[j].x * wv.x + lv[j].y * wv.y + lv[j].z * wv.z + lv[j].w * wv.w;
        }
        out[((size_t)b * 64 + o) * PX + px] = fmaxf(acc, 0.f);
    }
}

extern "C" void kernel_launch(void* const* d_in, const int* in_sizes, int n_in,
                              void* d_out, int out_size)
{
    const float* features = (const float*)d_in[0];
    const float* w_out = (const float*)d_in[17];
    const float* b_out = (const float*)d_in[18];
    float* out = (float*)d_out;

    bf16 *ft, *xs1, *hb, *wpk;
    float *cb, *g0, *g1, *last, *bc;
    cudaGetSymbolAddress((void**)&ft, g_ft);
    cudaGetSymbolAddress((void**)&xs1, g_xs1);
    cudaGetSymbolAddress((void**)&hb, g_hb);
    cudaGetSymbolAddress((void**)&cb, g_cb);
    cudaGetSymbolAddress((void**)&g0, g_g0);
    cudaGetSymbolAddress((void**)&g1, g_g1);
    cudaGetSymbolAddress((void**)&last, g_lastb);
    cudaGetSymbolAddress((void**)&wpk, g_wpk);
    cudaGetSymbolAddress((void**)&bc, g_bc);

    bf16* wih[4]; bf16* whh[3];
    for (int s = 0; s < 4; s++) wih[s] = wpk + (size_t)s * 589824;
    for (int s = 0; s < 3; s++) whh[s] = wpk + (size_t)4 * 589824 + (size_t)s * 294912;

    const int DSMEM = 3 * 32768;
    cudaFuncSetAttribute(conv_hmma<128, 0>, cudaFuncAttributeMaxDynamicSharedMemorySize, DSMEM);
    cudaFuncSetAttribute(conv_hmma<128, 2>, cudaFuncAttributeMaxDynamicSharedMemorySize, DSMEM);
    cudaFuncSetAttribute(conv_hmma<64, 1>,  cudaFuncAttributeMaxDynamicSharedMemorySize, DSMEM);
    cudaFuncSetAttribute(conv_hmma<64, 3>,  cudaFuncAttributeMaxDynamicSharedMemorySize, DSMEM);

    setptr_k<<<1, 1>>>((const float*)d_in[1], (const float*)d_in[5],
                       (const float*)d_in[9], (const float*)d_in[13],
                       (const float*)d_in[2], (const float*)d_in[6],
                       (const float*)d_in[10],
                       (const float*)d_in[3], (const float*)d_in[7],
                       (const float*)d_in[11], (const float*)d_in[15],
                       (const float*)d_in[4], (const float*)d_in[8],
                       (const float*)d_in[12], (const float*)d_in[16]);
    repack_all<<<dim3(1152, 7), 256>>>(wpk, bc);
    feat_tr_k<<<dim3(64, 4, 4), 256>>>(features);

    const size_t IMGZ = (size_t)PX * 256;
    const size_t CS = (size_t)PX * 64;
    const size_t HS = (size_t)2 * PX * 64;
    const int N16 = 16 * PX * 64, N8 = 8 * PX * 64;

    conv_hmma<128, 0><<<dim3(8, 2, 128), 256, DSMEM>>>(
        ft, wih[0], wih[1], bc, bc + 256, g0, nullptr, nullptr, nullptr, nullptr, 0);
    cell_k<<<N16 / 256, 256>>>(g0, cb, hb, xs1, nullptr, 0, 0, N16);
    for (int t = 1; t < TT; t++)
        conv_hmma<64, 1><<<dim3(8, 2, 16), 256, DSMEM>>>(
            hb, whh[0], whh[1], nullptr, nullptr, g0, cb, hb, xs1, nullptr, t);

    conv_hmma<128, 2><<<dim3(8, 2, 64), 256, DSMEM>>>(
        xs1, wih[2], nullptr, bc + 512, nullptr, g1, nullptr, nullptr, nullptr, nullptr, 0);
    conv_hmma<128, 2><<<dim3(8, 2, 8), 256, DSMEM>>>(
        xs1 + (size_t)56 * 2 * PX * 128, wih[3], nullptr, bc + 768, nullptr,
        g1 + 64 * IMGZ, nullptr, nullptr, nullptr, nullptr, 0);

    cell_k<<<N8 / 256, 256>>>(g1 + 64 * IMGZ, cb + 16 * CS, hb + 16 * HS,
                              nullptr, last, 1, 64, N8);
    cell_k<<<N8 / 256, 256>>>(g1, cb + 24 * CS, hb + 24 * HS, nullptr, nullptr, 1, 0, N8);
    for (int t = 1; t < TT; t++)
        conv_hmma<64, 3><<<dim3(8, 2, 8), 256, DSMEM>>>(
            hb + 24 * HS, whh[2], nullptr, nullptr, nullptr, g1,
            cb + 24 * CS, hb + 24 * HS, nullptr, (t == TT - 1) ? last : nullptr, t);

    head_k<<<dim3(8, 4), 256>>>(last, w_out, b_out, out);
}

// round 12
// speedup vs baseline: 3.9963x; 1.0740x over previous
#include <cuda_runtime.h>
#include <cuda_bf16.h>
#include <cstdint>

#define TT 8
#define PX 1024
typedef __nv_bfloat16 bf16;

__device__ __align__(16) bf16  g_ft[(size_t)64 * 2 * PX * 128];
__device__ __align__(16) bf16  g_xs1[(size_t)64 * 2 * PX * 128];
__device__ __align__(16) bf16  g_hb[(size_t)32 * 2 * PX * 64];
__device__ __align__(16) float g_cb[(size_t)32 * PX * 64];
__device__ __align__(16) float g_g0[(size_t)128 * PX * 256];
__device__ __align__(16) float g_g1[(size_t)72 * PX * 256];
__device__ __align__(16) float g_lastb[(size_t)8 * PX * 128];
__device__ __align__(16) bf16  g_wpk[(size_t)4 * 589824 + (size_t)3 * 294912];
__device__ __align__(16) float g_bc[4 * 256];
__device__ const float* g_wptr[8];
__device__ const float* g_biptr[4];
__device__ const float* g_bhptr[4];

__device__ __forceinline__ uint32_t smem_u32(const void* p) {
    uint32_t a;
    asm("{ .reg .u64 t; cvta.to.shared.u64 t, %1; cvt.u32.u64 %0, t; }" : "=r"(a) : "l"(p));
    return a;
}
__device__ __forceinline__ void ldsm4(uint32_t* r, uint32_t a) {
    asm volatile("ldmatrix.sync.aligned.m8n8.x4.shared.b16 {%0,%1,%2,%3}, [%4];"
        : "=r"(r[0]), "=r"(r[1]), "=r"(r[2]), "=r"(r[3]) : "r"(a));
}
__device__ __forceinline__ void mma16816(float* d, const uint32_t* a, const uint32_t* b) {
    asm volatile("mma.sync.aligned.m16n8k16.row.col.f32.bf16.bf16.f32 "
        "{%0,%1,%2,%3},{%4,%5,%6,%7},{%8,%9},{%0,%1,%2,%3};"
        : "+f"(d[0]), "+f"(d[1]), "+f"(d[2]), "+f"(d[3])
        : "r"(a[0]), "r"(a[1]), "r"(a[2]), "r"(a[3]), "r"(b[0]), "r"(b[1]));
}
__device__ __forceinline__ void cp16(uint32_t d, const void* s, uint32_t sz) {
    asm volatile("cp.async.cg.shared.global [%0], [%1], 16, %2;" :: "r"(d), "l"(s), "r"(sz) : "memory");
}
__device__ __forceinline__ void cp16f(uint32_t d, const void* s) {
    asm volatile("cp.async.cg.shared.global [%0], [%1], 16;" :: "r"(d), "l"(s) : "memory");
}
__device__ __forceinline__ void cp_commit() { asm volatile("cp.async.commit_group;" ::: "memory"); }
__device__ __forceinline__ void cp_wait0() { asm volatile("cp.async.wait_group 0;" ::: "memory"); }
__device__ __forceinline__ void cp_wait1() { asm volatile("cp.async.wait_group 1;" ::: "memory"); }
__device__ __forceinline__ float sigf(float x) { return 1.f / (1.f + __expf(-x)); }

__global__ void setptr_k(const float* w0, const float* w1, const float* w2, const float* w3,
                         const float* w4, const float* w5, const float* w6,
                         const float* bi0, const float* bi1, const float* bi2, const float* bi3,
                         const float* bh0, const float* bh1, const float* bh2, const float* bh3)
{
    g_wptr[0] = w0; g_wptr[1] = w1; g_wptr[2] = w2; g_wptr[3] = w3;
    g_wptr[4] = w4; g_wptr[5] = w5; g_wptr[6] = w6;
    g_biptr[0] = bi0; g_biptr[1] = bi1; g_biptr[2] = bi2; g_biptr[3] = bi3;
    g_bhptr[0] = bh0; g_bhptr[1] = bh1; g_bhptr[2] = bh2; g_bhptr[3] = bh3;
}

__global__ void repack_all(bf16* __restrict__ wdst, float* __restrict__ bc)
{
    int s = blockIdx.y;
    int cin = (s < 4) ? 128 : 64;
    int tot = 256 * cin * 9;
    int idx = blockIdx.x * 256 + threadIdx.x;
    bf16* dst = (s < 4) ? wdst + (size_t)s * 589824
                        : wdst + (size_t)4 * 589824 + (size_t)(s - 4) * 294912;
    if (idx < tot) {
        const float* w = g_wptr[s];
        int k = idx % 9, rest = idx / 9;
        int ci = rest % cin, g = rest / cin;
        int gp = (g & 63) * 4 + (g >> 6);
        float v = w[idx];
        bf16 hi = __float2bfloat16(v);
        bf16 lo = __float2bfloat16(v - __bfloat162float(hi));
        size_t o = ((size_t)k * 256 + gp) * cin + ci;
        dst[o] = hi;
        dst[(size_t)9 * 256 * cin + o] = lo;
    }
    if (s < 4 && blockIdx.x == 0 && threadIdx.x < 256) {
        int g = threadIdx.x;
        bc[s * 256 + (g & 63) * 4 + (g >> 6)] = g_biptr[s][g] + g_bhptr[s][g];
    }
}

__global__ void feat_tr_k(const float* __restrict__ f)
{
    __shared__ float s[32][257];
    int img = blockIdx.x, cbk = blockIdx.y, pb = blockIdx.z, tid = threadIdx.x;
    int b = img & 7, t = img >> 3;
    const float* src = f + ((size_t)(b * TT + t) * 128 + cbk * 32) * PX + pb * 256;
#pragma unroll 8
    for (int r = 0; r < 32; r++) s[r][tid] = src[(size_t)r * PX + tid];
    __syncthreads();
    int ci = tid & 31, pl = tid >> 5;
    bf16* dh = g_ft + (size_t)(img * 2) * PX * 128;
    bf16* dl = dh + (size_t)PX * 128;
#pragma unroll 8
    for (int wv = 0; wv < 32; wv++) {
        int p = pb * 256 + wv * 8 + pl;
        float v = s[ci][wv * 8 + pl];
        bf16 hi = __float2bfloat16(v);
        dh[(size_t)p * 128 + cbk * 32 + ci] = hi;
        dl[(size_t)p * 128 + cbk * 32 + ci] = __float2bfloat16(v - __bfloat162float(hi));
    }
}

// ---- conv3x3 implicit GEMM, term-major (proven), 3-stage cp.async.cg pipeline ----
template <int CIN, int MODE>
__global__ void __launch_bounds__(256, 2)
conv_hmma(const bf16* __restrict__ act, const bf16* __restrict__ wpa,
          const bf16* __restrict__ wpb, const float* __restrict__ biasa,
          const float* __restrict__ biasb, float* __restrict__ gB,
          float* __restrict__ cB, bf16* __restrict__ hB,
          bf16* __restrict__ xsB, float* __restrict__ lastB, int t)
{
    extern __shared__ __align__(16) char sm[];
    const int tid = threadIdx.x, lane = tid & 31, wid = tid >> 5;
    const int wM = wid & 3, wN = wid >> 2;
    const int ghalf = blockIdx.x, tile = blockIdx.y, z = blockIdx.z;

    const bf16* wp = wpa;
    const float* bias = biasa;
    int slot = z, aimg = 0, xslot = 0, choff = 0;
    if (MODE == 0) { int dir = z >> 6; slot = z & 63; if (dir) { wp = wpb; bias = biasb; } }
    else if (MODE == 1) {
        int dir = z >> 3, b_ = z & 7;
        if (dir) wp = wpb;
        int teff = dir ? 7 - t : t;
        aimg = dir * 64 + teff * 8 + b_;
        xslot = teff * 8 + b_; choff = dir * 64;
    } else if (MODE == 3) { aimg = t * 8 + z; }

    const size_t actps = (size_t)PX * CIN;
    const bf16* aimg_p = act + (size_t)slot * 2 * actps;
    const size_t wps = (size_t)9 * 256 * CIN;
    const uint32_t su = smem_u32(sm);

    float acc[2][8][4];
#pragma unroll
    for (int a = 0; a < 2; a++)
#pragma unroll
        for (int n = 0; n < 8; n++)
#pragma unroll
            for (int c = 0; c < 4; c++) acc[a][n][c] = 0.f;

    const int NH = CIN / 64, NIT = 27 * NH;
    const int lrow = tid >> 1, seg = (tid & 1) * 64;
    const int gpxA = tile * 128 + lrow;

    auto issue = [&](int it) {
        int buf = it % 3;
        int term = it / (9 * NH), rem = it - term * (9 * NH);
        int k = rem / NH, half = rem - k * NH;
        int pa = (term == 1), pbw = (term == 2);
        int ys = (gpxA >> 5) + k / 3 - 1, xsv = (gpxA & 31) + k % 3 - 1;
        bool v = ((unsigned)ys < 32u) && ((unsigned)xsv < 32u);
        const char* asrc = (const char*)(aimg_p + (size_t)pa * actps +
                           (v ? (size_t)(ys * 32 + xsv) * CIN : (size_t)0) + half * 64) + seg;
        const char* bsrc = (const char*)(wp + (size_t)pbw * wps +
                           ((size_t)k * 256 + ghalf * 128 + lrow) * CIN + half * 64) + seg;
        uint32_t ab = su + buf * 32768 + lrow * 128;
        uint32_t bb_ = ab + 16384;
        uint32_t sz = v ? 16u : 0u;
#pragma unroll
        for (int j = 0; j < 4; j++) {
            uint32_t off = seg + j * 16;
            uint32_t swz = off ^ ((lrow & 7) << 4);
            cp16(ab + swz, asrc + j * 16, sz);
            cp16f(bb_ + swz, bsrc + j * 16);
        }
        cp_commit();
    };

    const int aro = (lane & 7) + 8 * ((lane >> 3) & 1), acs = (lane >> 4) & 1;
    const int bro = (lane & 7) + 8 * ((lane >> 4) & 1), bcs = (lane >> 3) & 1;

    issue(0);
    issue(1);
    for (int it = 0; it < NIT; it++) {
        if (it < NIT - 1) cp_wait1(); else cp_wait0();
        __syncthreads();
        if (it + 2 < NIT) issue(it + 2);
        uint32_t sa = su + (it % 3) * 32768, sb = sa + 16384;
#pragma unroll
        for (int s = 0; s < 4; s++) {
            uint32_t af[2][4];
#pragma unroll
            for (int mi = 0; mi < 2; mi++) {
                int row = wM * 32 + mi * 16 + aro;
                ldsm4(af[mi], sa + row * 128 + ((2 * s + acs) ^ (row & 7)) * 16);
            }
#pragma unroll
            for (int np = 0; np < 4; np++) {
                uint32_t bfr[4];
                int row = wN * 64 + np * 16 + bro;
                ldsm4(bfr, sb + row * 128 + ((2 * s + bcs) ^ (row & 7)) * 16);
#pragma unroll
                for (int mi = 0; mi < 2; mi++) {
                    mma16816(acc[mi][np * 2],     af[mi], bfr);
                    mma16816(acc[mi][np * 2 + 1], af[mi], bfr + 2);
                }
            }
        }
    }
    __syncthreads();

    float* st = (float*)sm;
    const int r0 = wM * 32 + (lane >> 2), c0 = wN * 64 + (lane & 3) * 2;
#pragma unroll
    for (int mi = 0; mi < 2; mi++)
#pragma unroll
        for (int ni = 0; ni < 8; ni++) {
            int r = r0 + mi * 16, c = c0 + ni * 8;
            *(float2*)(st + r * 130 + c)       = *(float2*)acc[mi][ni];
            *(float2*)(st + (r + 8) * 130 + c) = *(float2*)(acc[mi][ni] + 2);
        }
    __syncthreads();

    if (MODE == 0 || MODE == 2) {
        float* gout = gB + (size_t)z * PX * 256;
        float4 bq = *(const float4*)(bias + ghalf * 128 + lane * 4);
#pragma unroll 1
        for (int it = 0; it < 16; it++) {
            int px = wid + 8 * it;
            float2 a01 = *(float2*)(st + px * 130 + lane * 4);
            float2 a23 = *(float2*)(st + px * 130 + lane * 4 + 2);
            float4 o = { a01.x + bq.x, a01.y + bq.y, a23.x + bq.z, a23.y + bq.w };
            *(float4*)(gout + (size_t)(tile * 128 + px) * 256 + ghalf * 128 + lane * 4) = o;
        }
    } else {
        const int gch = ghalf * 32 + lane;
#pragma unroll 1
        for (int it = 0; it < 16; it++) {
            int px = wid + 8 * it;
            int gpx = tile * 128 + px;
            float2 a01 = *(float2*)(st + px * 130 + lane * 4);
            float2 a23 = *(float2*)(st + px * 130 + lane * 4 + 2);
            float4 g4 = *(const float4*)(gB + ((size_t)aimg * PX + gpx) * 256 + gch * 4);
            float i_ = a01.x + g4.x, f_ = a01.y + g4.y;
            float g_ = a23.x + g4.z, o_ = a23.y + g4.w;
            size_t ci = ((size_t)z * PX + gpx) * 64 + gch;
            float cp = cB[ci];
            float cn = sigf(f_) * cp + sigf(i_) * tanhf(g_);
            float hn = sigf(o_) * tanhf(cn);
            cB[ci] = cn;
            bf16 hh_ = __float2bfloat16(hn);
            bf16 hl_ = __float2bfloat16(hn - __bfloat162float(hh_));
            size_t hi_ = ((size_t)z * 2 * PX + gpx) * 64 + gch;
            hB[hi_] = hh_;
            hB[hi_ + (size_t)PX * 64] = hl_;
            if (MODE == 1) {
                size_t xb = ((size_t)(xslot * 2) * PX + gpx) * 128 + choff + gch;
                xsB[xb] = hh_;
                xsB[xb + (size_t)PX * 128] = hl_;
            }
            if (MODE == 3 && lastB)
                lastB[((size_t)z * PX + gpx) * 128 + gch] = hn;
        }
    }
}

__global__ void cell_k(const float* __restrict__ gih, float* __restrict__ cB,
                       bf16* __restrict__ hB, bf16* __restrict__ xsB,
                       float* __restrict__ lastB, int mode, int lco, int n)
{
    int i = blockIdx.x * 256 + threadIdx.x;
    if (i >= n) return;
    int ch = i & 63, px = (i >> 6) & 1023, im = i >> 16;
    int gslot = im, xslot = 0, choff = 0;
    if (mode == 0) {
        int dir = im >> 3, b = im & 7;
        int teff = dir ? 7 : 0;
        gslot = dir * 64 + teff * 8 + b;
        xslot = teff * 8 + b; choff = dir * 64;
    }
    float4 g4 = *(const float4*)(gih + ((size_t)gslot * PX + px) * 256 + ch * 4);
    float cn = sigf(g4.x) * tanhf(g4.z);
    float hn = sigf(g4.w) * tanhf(cn);
    cB[i] = cn;
    bf16 hh_ = __float2bfloat16(hn);
    bf16 hl_ = __float2bfloat16(hn - __bfloat162float(hh_));
    size_t hb_ = ((size_t)im * 2 * PX + px) * 64 + ch;
    hB[hb_] = hh_;
    hB[hb_ + (size_t)PX * 64] = hl_;
    if (xsB) {
        size_t xb = ((size_t)(xslot * 2) * PX + px) * 128 + choff + ch;
        xsB[xb] = hh_;
        xsB[xb + (size_t)PX * 128] = hl_;
    }
    if (lastB) lastB[((size_t)im * PX + px) * 128 + lco + ch] = hn;
}

__global__ void __launch_bounds__(256) head_k(const float* __restrict__ last,
                                              const float* __restrict__ w,
                                              const float* __restrict__ bias,
                                              float* __restrict__ out)
{
    __shared__ float sw[8192];
    __shared__ float sb[64];
    int b = blockIdx.x, pb = blockIdx.y, tid = threadIdx.x;
    for (int i = tid; i < 8192; i += 256) sw[i] = w[i];
    if (tid < 64) sb[tid] = bias[tid];
    __syncthreads();
    int px = pb * 256 + tid;
    const float4* lrow = (const float4*)(last + ((size_t)b * PX + px) * 128);
    float4 lv[32];
#pragma unroll
    for (int j = 0; j < 32; j++) lv[j] = lrow[j];
#pragma unroll 1
    for (int o = 0; o < 64; o++) {
        const float4* wr = (const float4*)(sw + o * 128);
        float acc = sb[o];
#pragma unroll
        for (int j = 0; j < 32; j++) {
            float4 wv = wr[j];
            acc += lv[j].x * wv.x + lv[j].y * wv.y + lv[j].z * wv.z + lv[j].w * wv.w;
        }
        out[((size_t)b * 64 + o) * PX + px] = fmaxf(acc, 0.f);
    }
}

extern "C" void kernel_launch(void* const* d_in, const int* in_sizes, int n_in,
                              void* d_out, int out_size)
{
    const float* features = (const float*)d_in[0];
    const float* w_out = (const float*)d_in[17];
    const float* b_out = (const float*)d_in[18];
    float* out = (float*)d_out;

    bf16 *ft, *xs1, *hb, *wpk;
    float *cb, *g0, *g1, *last, *bc;
    cudaGetSymbolAddress((void**)&ft, g_ft);
    cudaGetSymbolAddress((void**)&xs1, g_xs1);
    cudaGetSymbolAddress((void**)&hb, g_hb);
    cudaGetSymbolAddress((void**)&cb, g_cb);
    cudaGetSymbolAddress((void**)&g0, g_g0);
    cudaGetSymbolAddress((void**)&g1, g_g1);
    cudaGetSymbolAddress((void**)&last, g_lastb);
    cudaGetSymbolAddress((void**)&wpk, g_wpk);
    cudaGetSymbolAddress((void**)&bc, g_bc);

    bf16* wih[4]; bf16* whh[3];
    for (int s = 0; s < 4; s++) wih[s] = wpk + (size_t)s * 589824;
    for (int s = 0; s < 3; s++) whh[s] = wpk + (size_t)4 * 589824 + (size_t)s * 294912;

    const int DSMEM = 3 * 32768;
    cudaFuncSetAttribute(conv_hmma<128, 0>, cudaFuncAttributeMaxDynamicSharedMemorySize, DSMEM);
    cudaFuncSetAttribute(conv_hmma<128, 2>, cudaFuncAttributeMaxDynamicSharedMemorySize, DSMEM);
    cudaFuncSetAttribute(conv_hmma<64, 1>,  cudaFuncAttributeMaxDynamicSharedMemorySize, DSMEM);
    cudaFuncSetAttribute(conv_hmma<64, 3>,  cudaFuncAttributeMaxDynamicSharedMemorySize, DSMEM);

    setptr_k<<<1, 1>>>((const float*)d_in[1], (const float*)d_in[5],
                       (const float*)d_in[9], (const float*)d_in[13],
                       (const float*)d_in[2], (const float*)d_in[6],
                       (const float*)d_in[10],
                       (const float*)d_in[3], (const float*)d_in[7],
                       (const float*)d_in[11], (const float*)d_in[15],
                       (const float*)d_in[4], (const float*)d_in[8],
                       (const float*)d_in[12], (const float*)d_in[16]);
    repack_all<<<dim3(1152, 7), 256>>>(wpk, bc);
    feat_tr_k<<<dim3(64, 4, 4), 256>>>(features);

    const size_t IMGZ = (size_t)PX * 256;
    const size_t CS = (size_t)PX * 64;
    const size_t HS = (size_t)2 * PX * 64;
    const int N16 = 16 * PX * 64, N8 = 8 * PX * 64;

    conv_hmma<128, 0><<<dim3(2, 8, 128), 256, DSMEM>>>(
        ft, wih[0], wih[1], bc, bc + 256, g0, nullptr, nullptr, nullptr, nullptr, 0);
    cell_k<<<N16 / 256, 256>>>(g0, cb, hb, xs1, nullptr, 0, 0, N16);
    for (int t = 1; t < TT; t++)
        conv_hmma<64, 1><<<dim3(2, 8, 16), 256, DSMEM>>>(
            hb, whh[0], whh[1], nullptr, nullptr, g0, cb, hb, xs1, nullptr, t);

    conv_hmma<128, 2><<<dim3(2, 8, 64), 256, DSMEM>>>(
        xs1, wih[2], nullptr, bc + 512, nullptr, g1, nullptr, nullptr, nullptr, nullptr, 0);
    conv_hmma<128, 2><<<dim3(2, 8, 8), 256, DSMEM>>>(
        xs1 + (size_t)56 * 2 * PX * 128, wih[3], nullptr, bc + 768, nullptr,
        g1 + 64 * IMGZ, nullptr, nullptr, nullptr, nullptr, 0);

    cell_k<<<N8 / 256, 256>>>(g1 + 64 * IMGZ, cb + 16 * CS, hb + 16 * HS,
                              nullptr, last, 1, 64, N8);
    cell_k<<<N8 / 256, 256>>>(g1, cb + 24 * CS, hb + 24 * HS, nullptr, nullptr, 1, 0, N8);
    for (int t = 1; t < TT; t++)
        conv_hmma<64, 3><<<dim3(2, 8, 8), 256, DSMEM>>>(
            hb + 24 * HS, whh[2], nullptr, nullptr, nullptr, g1,
            cb + 24 * CS, hb + 24 * HS, nullptr, (t == TT - 1) ? last : nullptr, t);

    head_k<<<dim3(8, 4), 256>>>(last, w_out, b_out, out);
}